// round 6
// baseline (speedup 1.0000x reference)
#include <cuda_runtime.h>
#include <cstdint>

#define N_NODES 50000
#define N_EDGES 400000
#define H 128
#define DEPTH 8
#define TILE_N 48      // nodes per block tile
#define XS3 52         // smem activation row stride (48 + 4 pad)
#define WSS 132        // smem weight tile row stride (128 + 4 pad)

typedef unsigned long long ull;

// ---------------- device scratch (no allocation allowed) ----------------
__device__ float g_agg[N_NODES * H];
__device__ float g_denom[N_NODES];
__device__ float g_p1[N_NODES];
__device__ float g_p2[N_NODES];
__device__ int   g_node_list[N_NODES];
__device__ int   g_deg[N_NODES];
__device__ int   g_row[N_NODES + 1];
__device__ int   g_cur[N_NODES];
__device__ int   g_es[N_EDGES];          // edge srcs grouped by dst (CSR)
__device__ int   g_cnts[32];
__device__ int   g_node_off[DEPTH + 1];
// fused + transposed weights (k-major, [128 k][384 rows])
__device__ float g_WbigT[128 * 384];   // (W_ih[:,:128] @ W_msg) transposed
__device__ float g_WhhT[128 * 384];
__device__ float g_bbig[384];          // b_ih + W_ih[:,:128] @ b_msg

// smem float offsets for k_gru dynamic smem
#define SM_WSA0  0
#define SM_WSA1  4224
#define SM_WSB0  8448
#define SM_WSB1  12672
#define SM_XS    16896              // 128 x 52 = 6656
#define SM_HS    23552              // 128 x 52 = 6656
#define SM_NT    30208              // 3 x 384 = 1152 (W_ih node-type columns)
#define SM_META  31360              // snode/sact/srd/stype: 4 x 48
#define SM_FLOATS 31552
#define SM_BYTES (SM_FLOATS * 4)

__device__ __forceinline__ int clamp_lvl(int l) { return l < 0 ? 0 : (l > 7 ? 7 : l); }
__device__ __forceinline__ float sig_(float x) { return 1.0f / (1.0f + __expf(-x)); }
__device__ __forceinline__ float tanh_(float x) { return 2.0f / (1.0f + __expf(-2.0f * x)) - 1.0f; }

__device__ __forceinline__ ull pack2(float lo, float hi) {
    ull r; asm("mov.b64 %0,{%1,%2};" : "=l"(r) : "f"(lo), "f"(hi)); return r;
}
__device__ __forceinline__ void unpack2(ull v, float& lo, float& hi) {
    asm("mov.b64 {%0,%1},%2;" : "=f"(lo), "=f"(hi) : "l"(v));
}
__device__ __forceinline__ ull fma2(ull a, ull b, ull c) {
    ull d; asm("fma.rn.f32x2 %0,%1,%2,%3;" : "=l"(d) : "l"(a), "l"(b), "l"(c)); return d;
}
__device__ __forceinline__ ull add2(ull a, ull b) {
    ull d; asm("add.rn.f32x2 %0,%1,%2;" : "=l"(d) : "l"(a), "l"(b)); return d;
}
__device__ __forceinline__ ull sig2(ull v) {
    float a, b; unpack2(v, a, b); return pack2(sig_(a), sig_(b));
}

// ---------------- setup kernels ----------------

__global__ __launch_bounds__(512) void k_zero() {
    int i = blockIdx.x * blockDim.x + threadIdx.x;
    int stride = gridDim.x * blockDim.x;
    for (int idx = i; idx < N_NODES; idx += stride) g_deg[idx] = 0;
    if (i < 32) g_cnts[i] = 0;
}

// W_big[r,m] = sum_j W_ih[r,j] * W_msg[j,m]; b_big[r] = b_ih[r] + sum_j W_ih[r,j]*b_msg[j]
__global__ __launch_bounds__(128) void k_fuse(const float* __restrict__ Wih,
                                              const float* __restrict__ Wmsg,
                                              const float* __restrict__ bih,
                                              const float* __restrict__ bmsg) {
    int r = blockIdx.x;        // 0..383
    int m = threadIdx.x;       // 0..127
    __shared__ float wr[128];
    wr[m] = Wih[r * 131 + m];
    __syncthreads();
    float s = 0.f;
#pragma unroll 8
    for (int j = 0; j < 128; j++) s += wr[j] * Wmsg[j * 128 + m];
    g_WbigT[m * 384 + r] = s;
    if (m == 0) {
        float b = bih[r];
        for (int j = 0; j < 128; j++) b += wr[j] * bmsg[j];
        g_bbig[r] = b;
    }
}

__global__ __launch_bounds__(256) void k_transpose(const float* __restrict__ Whh) {
    int i = blockIdx.x * blockDim.x + threadIdx.x;
    int stride = gridDim.x * blockDim.x;
    for (int idx = i; idx < 384 * 128; idx += stride) {
        int r = idx >> 7, k = idx & 127;
        g_WhhT[k * 384 + r] = Whh[idx];
    }
}

// edge degree (for CSR) + node level counts
__global__ __launch_bounds__(256) void k_degcount(const int* __restrict__ fnl,
                                                  const int* __restrict__ edst) {
    __shared__ int sc[8];
    int t = threadIdx.x;
    if (t < 8) sc[t] = 0;
    __syncthreads();
    int idx = blockIdx.x * blockDim.x + t;
    int stride = gridDim.x * blockDim.x;
    for (int i = idx; i < N_EDGES; i += stride)
        atomicAdd(&g_deg[__ldg(&edst[i])], 1);
    for (int i = idx; i < N_NODES; i += stride)
        atomicAdd(&sc[clamp_lvl(__ldg(&fnl[i]))], 1);
    __syncthreads();
    if (t < 8 && sc[t] > 0) atomicAdd(&g_cnts[t], sc[t]);
}

__global__ void k_scan() {
    if (threadIdx.x == 0 && blockIdx.x == 0) {
        int no = 0;
        for (int l = 0; l < 8; l++) {
            g_node_off[l] = no; no += g_cnts[l];
        }
        g_node_off[8] = no;
        for (int l = 0; l < 8; l++) g_cnts[16 + l] = g_node_off[l];
    }
}

__global__ __launch_bounds__(256) void k_nscatter(const int* __restrict__ fnl) {
    __shared__ int scnt[8];
    __shared__ int sbase[8];
    int t = threadIdx.x;
    if (t < 8) scnt[t] = 0;
    __syncthreads();
    int i = blockIdx.x * blockDim.x + t;
    int key = -1, lp = 0;
    if (i < N_NODES) {
        key = clamp_lvl(__ldg(&fnl[i]));
        lp = atomicAdd(&scnt[key], 1);
    }
    __syncthreads();
    if (t < 8 && scnt[t] > 0) sbase[t] = atomicAdd(&g_cnts[16 + t], scnt[t]);
    __syncthreads();
    if (key >= 0) g_node_list[sbase[key] + lp] = i;
}

// exclusive scan of g_deg -> g_row, g_cur (single block, 1024 threads)
#define SCAN_PER 49
__global__ __launch_bounds__(1024) void k_scan_deg() {
    __shared__ int wsum[32];
    int t = threadIdx.x;
    int base = t * SCAN_PER;
    int s = 0;
    for (int j = 0; j < SCAN_PER; j++) {
        int idx = base + j;
        if (idx < N_NODES) s += g_deg[idx];
    }
    int lane = t & 31, w = t >> 5;
    int v = s;
#pragma unroll
    for (int off = 1; off < 32; off <<= 1) {
        int n = __shfl_up_sync(0xffffffffu, v, off);
        if (lane >= off) v += n;
    }
    if (lane == 31) wsum[w] = v;
    __syncthreads();
    if (w == 0) {
        int wv = wsum[lane];
#pragma unroll
        for (int off = 1; off < 32; off <<= 1) {
            int n = __shfl_up_sync(0xffffffffu, wv, off);
            if (lane >= off) wv += n;
        }
        wsum[lane] = wv;
    }
    __syncthreads();
    int excl = v - s + (w > 0 ? wsum[w - 1] : 0);
    int run = excl;
    for (int j = 0; j < SCAN_PER; j++) {
        int idx = base + j;
        if (idx < N_NODES) {
            g_row[idx] = run;
            g_cur[idx] = run;
            run += g_deg[idx];
        }
    }
    if (t == 1023) g_row[N_NODES] = run;
}

__global__ __launch_bounds__(256) void k_escatter(const int* __restrict__ esrc,
                                                  const int* __restrict__ edst) {
    int i = blockIdx.x * blockDim.x + threadIdx.x;
    int stride = gridDim.x * blockDim.x;
    for (int e = i; e < N_EDGES; e += stride) {
        int d = __ldg(&edst[e]);
        int pos = atomicAdd(&g_cur[d], 1);
        g_es[pos] = __ldg(&esrc[e]);
    }
}

__global__ __launch_bounds__(256) void k_init(const float* __restrict__ ne,
                                              const float* __restrict__ wa,
                                              float* __restrict__ h) {
    int lane = threadIdx.x & 31;
    int w = (blockIdx.x * blockDim.x + threadIdx.x) >> 5;
    int nw = (gridDim.x * blockDim.x) >> 5;
    float4 a1 = *(const float4*)&wa[lane * 4];
    float4 a2 = *(const float4*)&wa[H + lane * 4];
    for (int n = w; n < N_NODES; n += nw) {
        float4 v = *(const float4*)&ne[(size_t)n * H + lane * 4];
        *(float4*)&h[(size_t)n * H + lane * 4] = v;
        float s1 = v.x * a1.x + v.y * a1.y + v.z * a1.z + v.w * a1.w;
        float s2 = v.x * a2.x + v.y * a2.y + v.z * a2.z + v.w * a2.w;
#pragma unroll
        for (int off = 16; off; off >>= 1) {
            s1 += __shfl_xor_sync(0xffffffffu, s1, off);
            s2 += __shfl_xor_sync(0xffffffffu, s2, off);
        }
        if (lane == 0) { g_p1[n] = s1; g_p2[n] = s2; }
    }
}

// ---------------- per-level edge pass (CSR, no atomics) ----------------
__global__ __launch_bounds__(256) void k_edge(const float* __restrict__ h,
                                              const float* __restrict__ b_attn,
                                              int level) {
    int start = g_node_off[level], end = g_node_off[level + 1];
    int lane = threadIdx.x & 31;
    int warp = (blockIdx.x * blockDim.x + threadIdx.x) >> 5;
    int nwarp = (gridDim.x * blockDim.x) >> 5;
    float b = __ldg(b_attn);
    for (int i = start + warp; i < end; i += nwarp) {
        int d = g_node_list[i];
        int r0 = g_row[d], r1 = g_row[d + 1];
        if (r0 == r1) { if (lane == 0) g_denom[d] = 0.f; continue; }
        float p2d = g_p2[d];
        float denom = 0.f;
        float4 acc = make_float4(0.f, 0.f, 0.f, 0.f);
#pragma unroll 2
        for (int e = r0; e < r1; e++) {
            int src = __ldg(&g_es[e]);
            float ee = g_p1[src] + p2d + b;
            ee = ee > 0.f ? ee : 0.2f * ee;
            float ex = __expf(ee);
            denom += ex;
            float4 hv = __ldg((const float4*)(h + (size_t)src * H + lane * 4));
            acc.x += ex * hv.x; acc.y += ex * hv.y;
            acc.z += ex * hv.z; acc.w += ex * hv.w;
        }
        *(float4*)&g_agg[(size_t)d * H + lane * 4] = acc;
        if (lane == 0) g_denom[d] = denom;
    }
}

// ---------------- dual GEMM over a 48-node tile ----------------
__device__ __forceinline__ void issue_tile(const float* __restrict__ WT, int rowBase,
                                           int kk, float* wsbuf, int t) {
#pragma unroll
    for (int p = 0; p < 4; p++) {
        int idx = t + p * 256;               // 0..1023
        int c = idx >> 5, seg = (idx & 31) << 2;
        unsigned dst = (unsigned)__cvta_generic_to_shared(wsbuf + c * WSS + seg);
        const float* src = WT + (size_t)(kk + c) * 384 + rowBase + seg;
        asm volatile("cp.async.cg.shared.global [%0],[%1],16;"
                     :: "r"(dst), "l"(src) : "memory");
    }
}

__device__ __forceinline__ void gemm48_dual(ull (&accA)[4][3], ull (&accB)[4][3],
                                            int rowBase,
                                            const float* xs, const float* hs,
                                            float* wsA0, float* wsA1,
                                            float* wsB0, float* wsB1,
                                            int i0, int nb0, int t) {
    __syncthreads();
    issue_tile(g_WbigT, rowBase, 0, wsA0, t);
    issue_tile(g_WhhT,  rowBase, 0, wsB0, t);
    asm volatile("cp.async.commit_group;" ::: "memory");
#pragma unroll
    for (int kt = 0; kt < 4; kt++) {
        asm volatile("cp.async.wait_group 0;" ::: "memory");
        __syncthreads();
        if (kt < 3) {
            issue_tile(g_WbigT, rowBase, (kt + 1) << 5, (kt & 1) ? wsA0 : wsA1, t);
            issue_tile(g_WhhT,  rowBase, (kt + 1) << 5, (kt & 1) ? wsB0 : wsB1, t);
            asm volatile("cp.async.commit_group;" ::: "memory");
        }
        const float* curA = (kt & 1) ? wsA1 : wsA0;
        const float* curB = (kt & 1) ? wsB1 : wsB0;
        const float* xrow = xs + (kt << 5) * XS3 + nb0;
        const float* hrow = hs + (kt << 5) * XS3 + nb0;
#pragma unroll 2
        for (int c = 0; c < 32; c++) {
            float4 wa = *(const float4*)&curA[c * WSS + i0];
            float4 wb = *(const float4*)&curB[c * WSS + i0];
            ull x0 = *(const ull*)(xrow + c * XS3);
            ull x1 = *(const ull*)(xrow + c * XS3 + 2);
            ull x2 = *(const ull*)(xrow + c * XS3 + 4);
            ull h0 = *(const ull*)(hrow + c * XS3);
            ull h1 = *(const ull*)(hrow + c * XS3 + 2);
            ull h2 = *(const ull*)(hrow + c * XS3 + 4);
            ull a0 = pack2(wa.x, wa.x), a1 = pack2(wa.y, wa.y);
            ull a2 = pack2(wa.z, wa.z), a3 = pack2(wa.w, wa.w);
            ull b0 = pack2(wb.x, wb.x), b1 = pack2(wb.y, wb.y);
            ull b2 = pack2(wb.z, wb.z), b3 = pack2(wb.w, wb.w);
            accA[0][0] = fma2(a0, x0, accA[0][0]);
            accA[0][1] = fma2(a0, x1, accA[0][1]);
            accA[0][2] = fma2(a0, x2, accA[0][2]);
            accB[0][0] = fma2(b0, h0, accB[0][0]);
            accB[0][1] = fma2(b0, h1, accB[0][1]);
            accB[0][2] = fma2(b0, h2, accB[0][2]);
            accA[1][0] = fma2(a1, x0, accA[1][0]);
            accA[1][1] = fma2(a1, x1, accA[1][1]);
            accA[1][2] = fma2(a1, x2, accA[1][2]);
            accB[1][0] = fma2(b1, h0, accB[1][0]);
            accB[1][1] = fma2(b1, h1, accB[1][1]);
            accB[1][2] = fma2(b1, h2, accB[1][2]);
            accA[2][0] = fma2(a2, x0, accA[2][0]);
            accA[2][1] = fma2(a2, x1, accA[2][1]);
            accA[2][2] = fma2(a2, x2, accA[2][2]);
            accB[2][0] = fma2(b2, h0, accB[2][0]);
            accB[2][1] = fma2(b2, h1, accB[2][1]);
            accB[2][2] = fma2(b2, h2, accB[2][2]);
            accA[3][0] = fma2(a3, x0, accA[3][0]);
            accA[3][1] = fma2(a3, x1, accA[3][1]);
            accA[3][2] = fma2(a3, x2, accA[3][2]);
            accB[3][0] = fma2(b3, h0, accB[3][0]);
            accB[3][1] = fma2(b3, h1, accB[3][1]);
            accB[3][2] = fma2(b3, h2, accB[3][2]);
        }
    }
}

__global__ __launch_bounds__(256, 1) void k_gru(
    float* __restrict__ h, const float* __restrict__ node_type,
    const float* __restrict__ Wih, const float* __restrict__ bhh,
    const float* __restrict__ Wattn, int level) {
    extern __shared__ __align__(16) float sm[];
    float* wsA0 = sm + SM_WSA0;
    float* wsA1 = sm + SM_WSA1;
    float* wsB0 = sm + SM_WSB0;
    float* wsB1 = sm + SM_WSB1;
    float* xs  = sm + SM_XS;
    float* hs  = sm + SM_HS;
    float* smnt = sm + SM_NT;
    int*   snode = (int*)(sm + SM_META);
    float* sact  = sm + SM_META + TILE_N;
    float* srd   = sm + SM_META + 2 * TILE_N;
    int*   stype = (int*)(sm + SM_META + 3 * TILE_N);

    int t = threadIdx.x;
    int start = g_node_off[level], end = g_node_off[level + 1];
    int cnt = end - start;
    int ntiles = (cnt + TILE_N - 1) / TILE_N;
    int lane = t & 31;
    int i0 = lane << 2;
    int warp = t >> 5;
    int nb0 = warp * 6;

    for (int idx = t; idx < 1152; idx += 256) {
        int c = idx % 3, r = idx / 3;
        smnt[c * 384 + r] = Wih[r * 131 + 128 + c];
    }

    for (int tile = blockIdx.x; tile < ntiles; tile += gridDim.x) {
        __syncthreads();
        if (t < TILE_N) {
            int slot = start + tile * TILE_N + t;
            int node = 0; float act = 0.f, rd = 0.f; int ty = 0;
            if (slot < end) {
                node = g_node_list[slot];
                float d = g_denom[node];
                if (d > 0.f) { act = 1.f; rd = 1.f / (d + 1e-16f); }
                float n1 = node_type[(size_t)node * 3 + 1];
                float n2 = node_type[(size_t)node * 3 + 2];
                ty = n1 > 0.5f ? 1 : (n2 > 0.5f ? 2 : 0);
            }
            snode[t] = node; sact[t] = act; srd[t] = rd; stype[t] = ty;
        }
        __syncthreads();
        for (int idx = t; idx < TILE_N * 32; idx += 256) {
            int n = idx % TILE_N, j4 = idx / TILE_N;
            int node = snode[n];
            float rd = srd[n];
            float4 av = *(const float4*)&g_agg[(size_t)node * H + (j4 << 2)];
            float4 hv = *(const float4*)&h[(size_t)node * H + (j4 << 2)];
            int jb = j4 << 2;
            xs[(jb + 0) * XS3 + n] = av.x * rd;
            xs[(jb + 1) * XS3 + n] = av.y * rd;
            xs[(jb + 2) * XS3 + n] = av.z * rd;
            xs[(jb + 3) * XS3 + n] = av.w * rd;
            hs[(jb + 0) * XS3 + n] = hv.x;
            hs[(jb + 1) * XS3 + n] = hv.y;
            hs[(jb + 2) * XS3 + n] = hv.z;
            hs[(jb + 3) * XS3 + n] = hv.w;
        }

        ull rr[4][3], zz[4][3];
        for (int chunk = 0; chunk < 3; chunk++) {
            ull ai[4][3], ah[4][3];
#pragma unroll
            for (int di = 0; di < 4; di++) {
                int row = chunk * H + i0 + di;
                float bb = g_bbig[row];
                float c0 = smnt[row], c1 = smnt[384 + row], c2 = smnt[768 + row];
                float b2 = bhh[row];
                ull bh2 = pack2(b2, b2);
#pragma unroll
                for (int p = 0; p < 3; p++) {
                    int n0 = nb0 + 2 * p;
                    int t0 = stype[n0], t1 = stype[n0 + 1];
                    float v0 = bb + (t0 == 1 ? c1 : (t0 == 2 ? c2 : c0));
                    float v1 = bb + (t1 == 1 ? c1 : (t1 == 2 ? c2 : c0));
                    ai[di][p] = pack2(v0, v1);
                    ah[di][p] = bh2;
                }
            }
            gemm48_dual(ai, ah, chunk * H, xs, hs, wsA0, wsA1, wsB0, wsB1, i0, nb0, t);
            if (chunk == 0) {
#pragma unroll
                for (int di = 0; di < 4; di++)
#pragma unroll
                    for (int p = 0; p < 3; p++)
                        rr[di][p] = sig2(add2(ai[di][p], ah[di][p]));
            } else if (chunk == 1) {
#pragma unroll
                for (int di = 0; di < 4; di++)
#pragma unroll
                    for (int p = 0; p < 3; p++)
                        zz[di][p] = sig2(add2(ai[di][p], ah[di][p]));
            } else {
                float4 a1 = *(const float4*)&Wattn[i0];
                float4 a2 = *(const float4*)&Wattn[H + i0];
#pragma unroll
                for (int p = 0; p < 3; p++) {
                    float v[2][4];
#pragma unroll
                    for (int di = 0; di < 4; di++) {
                        float in0, in1, hn0, hn1, r0, r1, z0, z1, h0, h1;
                        unpack2(ai[di][p], in0, in1);
                        unpack2(ah[di][p], hn0, hn1);
                        unpack2(rr[di][p], r0, r1);
                        unpack2(zz[di][p], z0, z1);
                        ull hold = *(const ull*)&hs[(i0 + di) * XS3 + nb0 + (p << 1)];
                        unpack2(hold, h0, h1);
                        float n0 = tanh_(in0 + r0 * hn0);
                        float n1 = tanh_(in1 + r1 * hn1);
                        v[0][di] = (1.f - z0) * n0 + z0 * h0;
                        v[1][di] = (1.f - z1) * n1 + z1 * h1;
                    }
#pragma unroll
                    for (int half = 0; half < 2; half++) {
                        int nn = nb0 + (p << 1) + half;
                        int node = snode[nn];
                        bool act = sact[nn] > 0.f;
                        if (act) {
                            *(float4*)&h[(size_t)node * H + i0] =
                                make_float4(v[half][0], v[half][1], v[half][2], v[half][3]);
                        }
                        float s1 = v[half][0] * a1.x + v[half][1] * a1.y +
                                   v[half][2] * a1.z + v[half][3] * a1.w;
                        float s2 = v[half][0] * a2.x + v[half][1] * a2.y +
                                   v[half][2] * a2.z + v[half][3] * a2.w;
#pragma unroll
                        for (int off = 16; off; off >>= 1) {
                            s1 += __shfl_xor_sync(0xffffffffu, s1, off);
                            s2 += __shfl_xor_sync(0xffffffffu, s2, off);
                        }
                        if (lane == 0 && act) { g_p1[node] = s1; g_p2[node] = s2; }
                    }
                }
            }
        }
    }
}

// ---------------- launch ----------------
extern "C" void kernel_launch(void* const* d_in, const int* in_sizes, int n_in,
                              void* d_out, int out_size) {
    const float* node_embedding = (const float*)d_in[0];
    const float* node_type      = (const float*)d_in[1];
    const float* W_attn         = (const float*)d_in[2];
    const float* b_attn         = (const float*)d_in[3];
    const float* W_msg          = (const float*)d_in[4];
    const float* b_msg          = (const float*)d_in[5];
    const float* W_ih           = (const float*)d_in[6];
    const float* W_hh           = (const float*)d_in[7];
    const float* b_ih           = (const float*)d_in[8];
    const float* b_hh           = (const float*)d_in[9];
    const int*   edge_src       = (const int*)d_in[10];
    const int*   edge_dst       = (const int*)d_in[11];
    const int*   fnl            = (const int*)d_in[12];
    float* h = (float*)d_out;

    cudaFuncSetAttribute(k_gru, cudaFuncAttributeMaxDynamicSharedMemorySize, SM_BYTES);

    k_zero<<<98, 512>>>();
    k_fuse<<<384, 128>>>(W_ih, W_msg, b_ih, b_msg);
    k_transpose<<<192, 256>>>(W_hh);
    k_degcount<<<1563, 256>>>(fnl, edge_dst);
    k_scan<<<1, 32>>>();
    k_nscatter<<<196, 256>>>(fnl);
    k_scan_deg<<<1, 1024>>>();
    k_escatter<<<1563, 256>>>(edge_src, edge_dst);
    k_init<<<6250, 256>>>(node_embedding, W_attn, h);

    for (int k = 1; k < DEPTH; k++) {
        k_edge<<<782, 256>>>(h, b_attn, k);
        k_gru<<<148, 256, SM_BYTES>>>(h, node_type, W_ih, b_hh, W_attn, k);
    }
}

// round 9
// speedup vs baseline: 1.1305x; 1.1305x over previous
#include <cuda_runtime.h>
#include <cstdint>

#define N_NODES 50000
#define N_EDGES 400000
#define H 128
#define DEPTH 8
#define TILE_N 64      // nodes per block tile
#define AST 132        // activation smem row stride (128 + 4)
#define WSS 132        // weight slab row stride (128 + 4)

// ---------------- device scratch (no allocation allowed) ----------------
__device__ float g_agg[N_NODES * H];
__device__ float g_denom[N_NODES];
__device__ float g_p1[N_NODES];
__device__ float g_p2[N_NODES];
__device__ int   g_node_list[N_NODES];
__device__ int   g_deg[N_NODES];
__device__ int   g_row[N_NODES + 1];
__device__ int   g_cur[N_NODES];
__device__ int   g_es[N_EDGES];          // edge srcs grouped by dst (CSR)
__device__ int   g_cnts[32];
__device__ int   g_node_off[DEPTH + 1];
// fused + transposed weights (k-major, [128 k][384 rows]), tf32-rounded
__device__ float g_WbigT[128 * 384];
__device__ float g_WhhT[128 * 384];
__device__ float g_bbig[384];

// smem float offsets for k_gru dynamic smem
#define SM_WS0   0                  // 32*132 = 4224
#define SM_WS1   4224
#define SM_XS    8448               // 64*132 = 8448 (tf32 agg*rd)
#define SM_HS    16896              // 64*132 (tf32 h)
#define SM_HSF   25344              // 64*132 (fp32 h, epilogue)
#define SM_NT    33792              // 3*384 node-type cols of W_ih
#define SM_BB    34944              // 384
#define SM_BH    35328              // 384
#define SM_SP1   35712              // 64
#define SM_SP2   35776              // 64
#define SM_SNODE 35840              // 64 (int)
#define SM_SACT  35904              // 64
#define SM_SRD   35968              // 64
#define SM_STYPE 36032              // 64 (int)
#define SM_FLOATS 36096
#define SM_BYTES (SM_FLOATS * 4)

__device__ __forceinline__ int clamp_lvl(int l) { return l < 0 ? 0 : (l > 7 ? 7 : l); }
__device__ __forceinline__ float sig_(float x) { return 1.0f / (1.0f + __expf(-x)); }
__device__ __forceinline__ float tanh_(float x) { return 2.0f / (1.0f + __expf(-2.0f * x)) - 1.0f; }
__device__ __forceinline__ float tf32f(float x) {
    unsigned u; asm("cvt.rna.tf32.f32 %0,%1;" : "=r"(u) : "f"(x));
    return __uint_as_float(u);
}

// ---------------- setup kernels ----------------

__global__ __launch_bounds__(512) void k_zero() {
    int i = blockIdx.x * blockDim.x + threadIdx.x;
    int stride = gridDim.x * blockDim.x;
    for (int idx = i; idx < N_NODES; idx += stride) g_deg[idx] = 0;
    if (i < 32) g_cnts[i] = 0;
}

// W_big = W_ih[:,:128] @ W_msg (tf32-rounded), b_big = b_ih + W_ih[:,:128] @ b_msg
__global__ __launch_bounds__(128) void k_fuse(const float* __restrict__ Wih,
                                              const float* __restrict__ Wmsg,
                                              const float* __restrict__ bih,
                                              const float* __restrict__ bmsg) {
    int r = blockIdx.x;        // 0..383
    int m = threadIdx.x;       // 0..127
    __shared__ float wr[128];
    wr[m] = Wih[r * 131 + m];
    __syncthreads();
    float s = 0.f;
#pragma unroll 8
    for (int j = 0; j < 128; j++) s += wr[j] * Wmsg[j * 128 + m];
    g_WbigT[m * 384 + r] = tf32f(s);
    if (m == 0) {
        float b = bih[r];
        for (int j = 0; j < 128; j++) b += wr[j] * bmsg[j];
        g_bbig[r] = b;
    }
}

__global__ __launch_bounds__(256) void k_transpose(const float* __restrict__ Whh) {
    int i = blockIdx.x * blockDim.x + threadIdx.x;
    int stride = gridDim.x * blockDim.x;
    for (int idx = i; idx < 384 * 128; idx += stride) {
        int r = idx >> 7, k = idx & 127;
        g_WhhT[k * 384 + r] = tf32f(Whh[idx]);
    }
}

__global__ __launch_bounds__(256) void k_degcount(const int* __restrict__ fnl,
                                                  const int* __restrict__ edst) {
    __shared__ int sc[8];
    int t = threadIdx.x;
    if (t < 8) sc[t] = 0;
    __syncthreads();
    int idx = blockIdx.x * blockDim.x + t;
    int stride = gridDim.x * blockDim.x;
    for (int i = idx; i < N_EDGES; i += stride)
        atomicAdd(&g_deg[__ldg(&edst[i])], 1);
    for (int i = idx; i < N_NODES; i += stride)
        atomicAdd(&sc[clamp_lvl(__ldg(&fnl[i]))], 1);
    __syncthreads();
    if (t < 8 && sc[t] > 0) atomicAdd(&g_cnts[t], sc[t]);
}

__global__ void k_scan() {
    if (threadIdx.x == 0 && blockIdx.x == 0) {
        int no = 0;
        for (int l = 0; l < 8; l++) { g_node_off[l] = no; no += g_cnts[l]; }
        g_node_off[8] = no;
        for (int l = 0; l < 8; l++) g_cnts[16 + l] = g_node_off[l];
    }
}

__global__ __launch_bounds__(256) void k_nscatter(const int* __restrict__ fnl) {
    __shared__ int scnt[8];
    __shared__ int sbase[8];
    int t = threadIdx.x;
    if (t < 8) scnt[t] = 0;
    __syncthreads();
    int i = blockIdx.x * blockDim.x + t;
    int key = -1, lp = 0;
    if (i < N_NODES) {
        key = clamp_lvl(__ldg(&fnl[i]));
        lp = atomicAdd(&scnt[key], 1);
    }
    __syncthreads();
    if (t < 8 && scnt[t] > 0) sbase[t] = atomicAdd(&g_cnts[16 + t], scnt[t]);
    __syncthreads();
    if (key >= 0) g_node_list[sbase[key] + lp] = i;
}

#define SCAN_PER 49
__global__ __launch_bounds__(1024) void k_scan_deg() {
    __shared__ int wsum[32];
    int t = threadIdx.x;
    int base = t * SCAN_PER;
    int s = 0;
    for (int j = 0; j < SCAN_PER; j++) {
        int idx = base + j;
        if (idx < N_NODES) s += g_deg[idx];
    }
    int lane = t & 31, w = t >> 5;
    int v = s;
#pragma unroll
    for (int off = 1; off < 32; off <<= 1) {
        int n = __shfl_up_sync(0xffffffffu, v, off);
        if (lane >= off) v += n;
    }
    if (lane == 31) wsum[w] = v;
    __syncthreads();
    if (w == 0) {
        int wv = wsum[lane];
#pragma unroll
        for (int off = 1; off < 32; off <<= 1) {
            int n = __shfl_up_sync(0xffffffffu, wv, off);
            if (lane >= off) wv += n;
        }
        wsum[lane] = wv;
    }
    __syncthreads();
    int run = v - s + (w > 0 ? wsum[w - 1] : 0);
    for (int j = 0; j < SCAN_PER; j++) {
        int idx = base + j;
        if (idx < N_NODES) {
            g_row[idx] = run;
            g_cur[idx] = run;
            run += g_deg[idx];
        }
    }
    if (t == 1023) g_row[N_NODES] = run;
}

__global__ __launch_bounds__(256) void k_escatter(const int* __restrict__ esrc,
                                                  const int* __restrict__ edst) {
    int i = blockIdx.x * blockDim.x + threadIdx.x;
    int stride = gridDim.x * blockDim.x;
    for (int e = i; e < N_EDGES; e += stride) {
        int d = __ldg(&edst[e]);
        int pos = atomicAdd(&g_cur[d], 1);
        g_es[pos] = __ldg(&esrc[e]);
    }
}

__global__ __launch_bounds__(256) void k_init(const float* __restrict__ ne,
                                              const float* __restrict__ wa,
                                              float* __restrict__ h) {
    int lane = threadIdx.x & 31;
    int w = (blockIdx.x * blockDim.x + threadIdx.x) >> 5;
    int nw = (gridDim.x * blockDim.x) >> 5;
    float4 a1 = *(const float4*)&wa[lane * 4];
    float4 a2 = *(const float4*)&wa[H + lane * 4];
    for (int n = w; n < N_NODES; n += nw) {
        float4 v = *(const float4*)&ne[(size_t)n * H + lane * 4];
        *(float4*)&h[(size_t)n * H + lane * 4] = v;
        float s1 = v.x * a1.x + v.y * a1.y + v.z * a1.z + v.w * a1.w;
        float s2 = v.x * a2.x + v.y * a2.y + v.z * a2.z + v.w * a2.w;
#pragma unroll
        for (int off = 16; off; off >>= 1) {
            s1 += __shfl_xor_sync(0xffffffffu, s1, off);
            s2 += __shfl_xor_sync(0xffffffffu, s2, off);
        }
        if (lane == 0) { g_p1[n] = s1; g_p2[n] = s2; }
    }
}

// ---------------- per-level edge pass (CSR, no atomics) ----------------
__global__ __launch_bounds__(256) void k_edge(const float* __restrict__ h,
                                              const float* __restrict__ b_attn,
                                              int level) {
    int start = g_node_off[level], end = g_node_off[level + 1];
    int lane = threadIdx.x & 31;
    int warp = (blockIdx.x * blockDim.x + threadIdx.x) >> 5;
    int nwarp = (gridDim.x * blockDim.x) >> 5;
    float b = __ldg(b_attn);
    for (int i = start + warp; i < end; i += nwarp) {
        int d = g_node_list[i];
        int r0 = g_row[d], r1 = g_row[d + 1];
        if (r0 == r1) { if (lane == 0) g_denom[d] = 0.f; continue; }
        float p2d = g_p2[d];
        float denom = 0.f;
        float4 acc = make_float4(0.f, 0.f, 0.f, 0.f);
#pragma unroll 2
        for (int e = r0; e < r1; e++) {
            int src = __ldg(&g_es[e]);
            float ee = g_p1[src] + p2d + b;
            ee = ee > 0.f ? ee : 0.2f * ee;
            float ex = __expf(ee);
            denom += ex;
            float4 hv = __ldg((const float4*)(h + (size_t)src * H + lane * 4));
            acc.x += ex * hv.x; acc.y += ex * hv.y;
            acc.z += ex * hv.z; acc.w += ex * hv.w;
        }
        *(float4*)&g_agg[(size_t)d * H + lane * 4] = acc;
        if (lane == 0) g_denom[d] = denom;
    }
}

// ---------------- tf32 tensor-core GRU ----------------
// block = 256 threads = 8 warps. warp -> (mw = warp&3: nodes mw*16; nw = warp>>2: rows nw*64)
// mma.m16n8k8: D[16 nodes x 8 rows]; warp covers 16 nodes x 64 rows = 8 n8 frags.

__device__ __forceinline__ void issue_slab(const float* __restrict__ WT, int rowBase,
                                           int k0, float* wsbuf, int t) {
#pragma unroll
    for (int p = 0; p < 4; p++) {
        int idx = t + p * 256;               // 0..1023
        int k = idx >> 5, n4 = (idx & 31) << 2;
        unsigned dst = (unsigned)__cvta_generic_to_shared(wsbuf + k * WSS + n4);
        const float* src = WT + (size_t)(k0 + k) * 384 + rowBase + n4;
        asm volatile("cp.async.cg.shared.global [%0],[%1],16;"
                     :: "r"(dst), "l"(src) : "memory");
    }
}

// d[f][0]=D[m0+grp][rb+f*8+2*t4], d[f][1]=+1 col, d[f][2]=D[m0+grp+8][...], d[f][3]=+1
__device__ __forceinline__ void mma_gemm(float (&d)[8][4], const float* __restrict__ WT,
                                         int rowBase, const float* act,
                                         float* ws0, float* ws1,
                                         int m0, int nw64, int grp, int t4, int t) {
    __syncthreads();                       // prior consumers of ws done
    issue_slab(WT, rowBase, 0, ws0, t);
    asm volatile("cp.async.commit_group;" ::: "memory");
    const unsigned* au = (const unsigned*)act;
#pragma unroll
    for (int s = 0; s < 4; s++) {
        asm volatile("cp.async.wait_group 0;" ::: "memory");
        __syncthreads();
        if (s < 3) {
            issue_slab(WT, rowBase, (s + 1) << 5, (s & 1) ? ws0 : ws1, t);
            asm volatile("cp.async.commit_group;" ::: "memory");
        }
        const unsigned* cur = (const unsigned*)((s & 1) ? ws1 : ws0);
        int K0 = s << 5;
#pragma unroll
        for (int k8 = 0; k8 < 4; k8++) {
            int kb = k8 << 3;
            unsigned a0 = au[(m0 + grp) * AST + K0 + kb + t4];
            unsigned a1 = au[(m0 + grp + 8) * AST + K0 + kb + t4];
            unsigned a2 = au[(m0 + grp) * AST + K0 + kb + t4 + 4];
            unsigned a3 = au[(m0 + grp + 8) * AST + K0 + kb + t4 + 4];
#pragma unroll
            for (int f = 0; f < 8; f++) {
                int n = nw64 + (f << 3) + grp;
                unsigned b0 = cur[(kb + t4) * WSS + n];
                unsigned b1 = cur[(kb + t4 + 4) * WSS + n];
                asm volatile(
                    "mma.sync.aligned.m16n8k8.row.col.f32.tf32.tf32.f32 "
                    "{%0,%1,%2,%3},{%4,%5,%6,%7},{%8,%9},{%0,%1,%2,%3};"
                    : "+f"(d[f][0]), "+f"(d[f][1]), "+f"(d[f][2]), "+f"(d[f][3])
                    : "r"(a0), "r"(a1), "r"(a2), "r"(a3), "r"(b0), "r"(b1));
            }
        }
    }
}

__global__ __launch_bounds__(256, 1) void k_gru(
    float* __restrict__ h, const float* __restrict__ node_type,
    const float* __restrict__ Wih, const float* __restrict__ bhh,
    const float* __restrict__ Wattn, int level) {
    extern __shared__ __align__(16) float sm[];
    float* ws0  = sm + SM_WS0;
    float* ws1  = sm + SM_WS1;
    float* xs   = sm + SM_XS;
    float* hs   = sm + SM_HS;
    float* hsf  = sm + SM_HSF;
    float* smnt = sm + SM_NT;
    float* sbb  = sm + SM_BB;
    float* sbh  = sm + SM_BH;
    float* sp1  = sm + SM_SP1;
    float* sp2  = sm + SM_SP2;
    int*   snode = (int*)(sm + SM_SNODE);
    float* sact  = sm + SM_SACT;
    float* srd   = sm + SM_SRD;
    int*   stype = (int*)(sm + SM_STYPE);

    int t = threadIdx.x;
    int start = g_node_off[level], end = g_node_off[level + 1];
    int cnt = end - start;
    int ntiles = (cnt + TILE_N - 1) / TILE_N;
    int lane = t & 31;
    int warp = t >> 5;
    int grp = lane >> 2;        // 0..7
    int t4 = lane & 3;          // 0..3
    int m0 = (warp & 3) << 4;   // node base within tile: 0,16,32,48
    int nw64 = (warp >> 2) << 6; // row half: 0 or 64

    // stage constants once per block
    for (int idx = t; idx < 1152; idx += 256) {
        int c = idx % 3, r = idx / 3;
        smnt[c * 384 + r] = Wih[r * 131 + 128 + c];
    }
    for (int idx = t; idx < 384; idx += 256) {
        sbb[idx] = g_bbig[idx];
        sbh[idx] = bhh[idx];
    }

    for (int tile = blockIdx.x; tile < ntiles; tile += gridDim.x) {
        __syncthreads();          // constants ready / prior tile fully done
        if (t < TILE_N) {
            int slot = start + tile * TILE_N + t;
            int node = 0; float act = 0.f, rd = 0.f; int ty = 0;
            if (slot < end) {
                node = g_node_list[slot];
                float d = g_denom[node];
                if (d > 0.f) { act = 1.f; rd = 1.f / (d + 1e-16f); }
                float n1 = node_type[(size_t)node * 3 + 1];
                float n2 = node_type[(size_t)node * 3 + 2];
                ty = n1 > 0.5f ? 1 : (n2 > 0.5f ? 2 : 0);
            }
            snode[t] = node; sact[t] = act; srd[t] = rd; stype[t] = ty;
            sp1[t] = 0.f; sp2[t] = 0.f;
        }
        __syncthreads();
        // stage activations: xs = tf32(agg*rd), hs = tf32(h), hsf = h (node-major)
        for (int idx = t; idx < TILE_N * 32; idx += 256) {
            int n = idx & 63, j4 = idx >> 6;
            int node = snode[n];
            float rd = srd[n];
            float4 av = *(const float4*)&g_agg[(size_t)node * H + (j4 << 2)];
            float4 hv = *(const float4*)&h[(size_t)node * H + (j4 << 2)];
            int base = n * AST + (j4 << 2);
            xs[base + 0] = tf32f(av.x * rd);
            xs[base + 1] = tf32f(av.y * rd);
            xs[base + 2] = tf32f(av.z * rd);
            xs[base + 3] = tf32f(av.w * rd);
            hs[base + 0] = tf32f(hv.x);
            hs[base + 1] = tf32f(hv.y);
            hs[base + 2] = tf32f(hv.z);
            hs[base + 3] = tf32f(hv.w);
            *(float4*)&hsf[base] = hv;
        }
        // (mma_gemm entry sync covers staging visibility)

        int ty_lo = 0, ty_hi = 0;
        float rr[8][4], zz[8][4];
        for (int chunk = 0; chunk < 3; chunk++) {
            float dx[8][4], dh[8][4];
#pragma unroll
            for (int f = 0; f < 8; f++)
#pragma unroll
                for (int j = 0; j < 4; j++) { dx[f][j] = 0.f; dh[f][j] = 0.f; }
            mma_gemm(dx, g_WbigT, chunk * H, xs, ws0, ws1, m0, nw64, grp, t4, t);
            mma_gemm(dh, g_WhhT,  chunk * H, hs, ws0, ws1, m0, nw64, grp, t4, t);
            if (chunk == 0) { ty_lo = stype[m0 + grp]; ty_hi = stype[m0 + grp + 8]; }
            int rb = chunk * H;
            if (chunk < 2) {
#pragma unroll
                for (int f = 0; f < 8; f++) {
                    int feat0 = nw64 + (f << 3) + (t4 << 1);
                    float bb0 = sbb[rb + feat0],  bb1 = sbb[rb + feat0 + 1];
                    float bh0 = sbh[rb + feat0],  bh1 = sbh[rb + feat0 + 1];
                    float clo0 = smnt[ty_lo * 384 + rb + feat0];
                    float clo1 = smnt[ty_lo * 384 + rb + feat0 + 1];
                    float chi0 = smnt[ty_hi * 384 + rb + feat0];
                    float chi1 = smnt[ty_hi * 384 + rb + feat0 + 1];
                    float g0 = sig_(dx[f][0] + bb0 + clo0 + dh[f][0] + bh0);
                    float g1 = sig_(dx[f][1] + bb1 + clo1 + dh[f][1] + bh1);
                    float g2 = sig_(dx[f][2] + bb0 + chi0 + dh[f][2] + bh0);
                    float g3 = sig_(dx[f][3] + bb1 + chi1 + dh[f][3] + bh1);
                    if (chunk == 0) { rr[f][0]=g0; rr[f][1]=g1; rr[f][2]=g2; rr[f][3]=g3; }
                    else            { zz[f][0]=g0; zz[f][1]=g1; zz[f][2]=g2; zz[f][3]=g3; }
                }
            } else {
                int nl_lo = m0 + grp, nl_hi = m0 + grp + 8;
                int node_lo = snode[nl_lo], node_hi = snode[nl_hi];
                bool act_lo = sact[nl_lo] > 0.f, act_hi = sact[nl_hi] > 0.f;
                float s1lo = 0.f, s2lo = 0.f, s1hi = 0.f, s2hi = 0.f;
#pragma unroll
                for (int f = 0; f < 8; f++) {
                    int feat0 = nw64 + (f << 3) + (t4 << 1);
                    float bb0 = sbb[rb + feat0],  bb1 = sbb[rb + feat0 + 1];
                    float bh0 = sbh[rb + feat0],  bh1 = sbh[rb + feat0 + 1];
                    float clo0 = smnt[ty_lo * 384 + rb + feat0];
                    float clo1 = smnt[ty_lo * 384 + rb + feat0 + 1];
                    float chi0 = smnt[ty_hi * 384 + rb + feat0];
                    float chi1 = smnt[ty_hi * 384 + rb + feat0 + 1];
                    float n0 = tanh_(dx[f][0] + bb0 + clo0 + rr[f][0] * (dh[f][0] + bh0));
                    float n1 = tanh_(dx[f][1] + bb1 + clo1 + rr[f][1] * (dh[f][1] + bh1));
                    float n2 = tanh_(dx[f][2] + bb0 + chi0 + rr[f][2] * (dh[f][2] + bh0));
                    float n3 = tanh_(dx[f][3] + bb1 + chi1 + rr[f][3] * (dh[f][3] + bh1));
                    float ho0 = hsf[nl_lo * AST + feat0];
                    float ho1 = hsf[nl_lo * AST + feat0 + 1];
                    float ho2 = hsf[nl_hi * AST + feat0];
                    float ho3 = hsf[nl_hi * AST + feat0 + 1];
                    float v0 = (1.f - zz[f][0]) * n0 + zz[f][0] * ho0;
                    float v1 = (1.f - zz[f][1]) * n1 + zz[f][1] * ho1;
                    float v2 = (1.f - zz[f][2]) * n2 + zz[f][2] * ho2;
                    float v3 = (1.f - zz[f][3]) * n3 + zz[f][3] * ho3;
                    if (act_lo)
                        *(float2*)&h[(size_t)node_lo * H + feat0] = make_float2(v0, v1);
                    if (act_hi)
                        *(float2*)&h[(size_t)node_hi * H + feat0] = make_float2(v2, v3);
                    float2 wa1 = *(const float2*)&Wattn[feat0];
                    float2 wa2 = *(const float2*)&Wattn[H + feat0];
                    s1lo += v0 * wa1.x + v1 * wa1.y;
                    s2lo += v0 * wa2.x + v1 * wa2.y;
                    s1hi += v2 * wa1.x + v3 * wa1.y;
                    s2hi += v2 * wa2.x + v3 * wa2.y;
                }
                atomicAdd(&sp1[nl_lo], s1lo);
                atomicAdd(&sp2[nl_lo], s2lo);
                atomicAdd(&sp1[nl_hi], s1hi);
                atomicAdd(&sp2[nl_hi], s2hi);
            }
        }
        __syncthreads();
        if (t < TILE_N && sact[t] > 0.f) {
            int node = snode[t];
            g_p1[node] = sp1[t];
            g_p2[node] = sp2[t];
        }
    }
}

// ---------------- launch ----------------
extern "C" void kernel_launch(void* const* d_in, const int* in_sizes, int n_in,
                              void* d_out, int out_size) {
    const float* node_embedding = (const float*)d_in[0];
    const float* node_type      = (const float*)d_in[1];
    const float* W_attn         = (const float*)d_in[2];
    const float* b_attn         = (const float*)d_in[3];
    const float* W_msg          = (const float*)d_in[4];
    const float* b_msg          = (const float*)d_in[5];
    const float* W_ih           = (const float*)d_in[6];
    const float* W_hh           = (const float*)d_in[7];
    const float* b_ih           = (const float*)d_in[8];
    const float* b_hh           = (const float*)d_in[9];
    const int*   edge_src       = (const int*)d_in[10];
    const int*   edge_dst       = (const int*)d_in[11];
    const int*   fnl            = (const int*)d_in[12];
    float* h = (float*)d_out;

    cudaFuncSetAttribute(k_gru, cudaFuncAttributeMaxDynamicSharedMemorySize, SM_BYTES);

    k_zero<<<98, 512>>>();
    k_fuse<<<384, 128>>>(W_ih, W_msg, b_ih, b_msg);
    k_transpose<<<192, 256>>>(W_hh);
    k_degcount<<<1563, 256>>>(fnl, edge_dst);
    k_scan<<<1, 32>>>();
    k_nscatter<<<196, 256>>>(fnl);
    k_scan_deg<<<1, 1024>>>();
    k_escatter<<<1563, 256>>>(edge_src, edge_dst);
    k_init<<<6250, 256>>>(node_embedding, W_attn, h);

    for (int k = 1; k < DEPTH; k++) {
        k_edge<<<782, 256>>>(h, b_attn, k);
        k_gru<<<148, 256, SM_BYTES>>>(h, node_type, W_ih, b_hh, W_attn, k);
    }
}

// round 10
// speedup vs baseline: 1.3799x; 1.2206x over previous
#include <cuda_runtime.h>
#include <cuda_fp16.h>
#include <cstdint>

#define N_NODES 50000
#define N_EDGES 400000
#define H 128
#define DEPTH 8
#define TILE_N 64      // nodes per block tile
#define ASTH 136       // activation smem row stride in halves (128 + 8)
#define ASTF 132       // fp32 h epilogue stride (128 + 4)
#define WSTH 40        // weight slab row stride in halves (32 + 8)

// ---------------- device scratch (no allocation allowed) ----------------
__device__ float  g_agg[N_NODES * H];
__device__ float  g_denom[N_NODES];
__device__ float  g_p1[N_NODES];
__device__ float  g_p2[N_NODES];
__device__ int    g_node_list[N_NODES];
__device__ int    g_deg[N_NODES];
__device__ int    g_row[N_NODES + 1];
__device__ int    g_cur[N_NODES];
__device__ int    g_es[N_EDGES];          // edge srcs grouped by dst (CSR)
__device__ int    g_cnts[32];
__device__ int    g_node_off[DEPTH + 1];
// fused weights, ROW-major [384 rows][128 k], fp16
__device__ __half g_WbigH[384 * 128];     // W_ih[:,:128] @ W_msg
__device__ __half g_WhhH[384 * 128];
__device__ float  g_bbig[384];            // b_ih + W_ih[:,:128] @ b_msg

// smem byte offsets for k_gru dynamic smem
#define SMB_WS0   0                 // 128*40 halves = 10240 B
#define SMB_WS1   10240
#define SMB_XS    20480             // 64*136 halves = 17408 B
#define SMB_HS    37888             // 17408 B
#define SMB_HSF   55296             // 64*132 fp32 = 33792 B
#define SMB_NT    89088             // 3*384 fp32 = 4608 B
#define SMB_BB    93696             // 1536 B
#define SMB_BH    95232             // 1536 B
#define SMB_SP1   96768             // 256 B
#define SMB_SP2   97024
#define SMB_SNODE 97280
#define SMB_SACT  97536
#define SMB_SRD   97792
#define SMB_STYPE 98048
#define SMB_TOTAL 98304

__device__ __forceinline__ int clamp_lvl(int l) { return l < 0 ? 0 : (l > 7 ? 7 : l); }
__device__ __forceinline__ float sig_(float x) { return 1.0f / (1.0f + __expf(-x)); }
__device__ __forceinline__ float tanh_(float x) { return 2.0f / (1.0f + __expf(-2.0f * x)) - 1.0f; }

// ---------------- setup: fuse W_big + convert Whh + zero deg/cnts ----------------
__global__ __launch_bounds__(128) void k_setup(const float* __restrict__ Wih,
                                               const float* __restrict__ Wmsg,
                                               const float* __restrict__ bih,
                                               const float* __restrict__ bmsg,
                                               const float* __restrict__ Whh) {
    int r = blockIdx.x;        // 0..383
    int m = threadIdx.x;       // 0..127
    __shared__ float wr[128];
    wr[m] = Wih[r * 131 + m];
    __syncthreads();
    float s = 0.f;
#pragma unroll 8
    for (int j = 0; j < 128; j++) s += wr[j] * Wmsg[j * 128 + m];
    g_WbigH[r * 128 + m] = __float2half(s);
    if (m == 0) {
        float b = bih[r];
        for (int j = 0; j < 128; j++) b += wr[j] * bmsg[j];
        g_bbig[r] = b;
    }
    int gid = r * 128 + m;                       // 0..49151
    g_WhhH[gid] = __float2half(Whh[gid]);        // exactly 384*128 elements
    for (int idx = gid; idx < N_NODES; idx += 384 * 128) g_deg[idx] = 0;
    if (gid < 32) g_cnts[gid] = 0;
}

__global__ __launch_bounds__(256) void k_degcount(const int* __restrict__ fnl,
                                                  const int* __restrict__ edst) {
    __shared__ int sc[8];
    int t = threadIdx.x;
    if (t < 8) sc[t] = 0;
    __syncthreads();
    int idx = blockIdx.x * blockDim.x + t;
    int stride = gridDim.x * blockDim.x;
    for (int i = idx; i < N_EDGES; i += stride)
        atomicAdd(&g_deg[__ldg(&edst[i])], 1);
    for (int i = idx; i < N_NODES; i += stride)
        atomicAdd(&sc[clamp_lvl(__ldg(&fnl[i]))], 1);
    __syncthreads();
    if (t < 8 && sc[t] > 0) atomicAdd(&g_cnts[t], sc[t]);
}

// level scan (thread 0) + exclusive degree scan -> g_row/g_cur (1024 threads)
#define SCAN_PER 49
__global__ __launch_bounds__(1024) void k_scandeg() {
    __shared__ int wsum[32];
    int t = threadIdx.x;
    if (t == 0) {
        int no = 0;
        for (int l = 0; l < 8; l++) { g_node_off[l] = no; no += g_cnts[l]; }
        g_node_off[8] = no;
        for (int l = 0; l < 8; l++) g_cnts[16 + l] = g_node_off[l];
    }
    int base = t * SCAN_PER;
    int s = 0;
    for (int j = 0; j < SCAN_PER; j++) {
        int idx = base + j;
        if (idx < N_NODES) s += g_deg[idx];
    }
    int lane = t & 31, w = t >> 5;
    int v = s;
#pragma unroll
    for (int off = 1; off < 32; off <<= 1) {
        int n = __shfl_up_sync(0xffffffffu, v, off);
        if (lane >= off) v += n;
    }
    if (lane == 31) wsum[w] = v;
    __syncthreads();
    if (w == 0) {
        int wv = wsum[lane];
#pragma unroll
        for (int off = 1; off < 32; off <<= 1) {
            int n = __shfl_up_sync(0xffffffffu, wv, off);
            if (lane >= off) wv += n;
        }
        wsum[lane] = wv;
    }
    __syncthreads();
    int run = v - s + (w > 0 ? wsum[w - 1] : 0);
    for (int j = 0; j < SCAN_PER; j++) {
        int idx = base + j;
        if (idx < N_NODES) {
            g_row[idx] = run;
            g_cur[idx] = run;
            run += g_deg[idx];
        }
    }
    if (t == 1023) g_row[N_NODES] = run;
}

// node scatter (by level) + edge scatter (CSR fill), one kernel
__global__ __launch_bounds__(256) void k_scatter(const int* __restrict__ fnl,
                                                 const int* __restrict__ esrc,
                                                 const int* __restrict__ edst) {
    __shared__ int scnt[8];
    __shared__ int sbase[8];
    int t = threadIdx.x;
    if (t < 8) scnt[t] = 0;
    __syncthreads();
    int i = blockIdx.x * blockDim.x + t;
    int key = -1, lp = 0;
    if (i < N_NODES) {
        key = clamp_lvl(__ldg(&fnl[i]));
        lp = atomicAdd(&scnt[key], 1);
    } else if (i < N_NODES + N_EDGES) {
        int e = i - N_NODES;
        int d = __ldg(&edst[e]);
        int pos = atomicAdd(&g_cur[d], 1);
        g_es[pos] = __ldg(&esrc[e]);
    }
    __syncthreads();
    if (t < 8 && scnt[t] > 0) sbase[t] = atomicAdd(&g_cnts[16 + t], scnt[t]);
    __syncthreads();
    if (key >= 0) g_node_list[sbase[key] + lp] = i;
}

__global__ __launch_bounds__(256) void k_init(const float* __restrict__ ne,
                                              const float* __restrict__ wa,
                                              float* __restrict__ h) {
    int lane = threadIdx.x & 31;
    int w = (blockIdx.x * blockDim.x + threadIdx.x) >> 5;
    int nw = (gridDim.x * blockDim.x) >> 5;
    float4 a1 = *(const float4*)&wa[lane * 4];
    float4 a2 = *(const float4*)&wa[H + lane * 4];
    for (int n = w; n < N_NODES; n += nw) {
        float4 v = *(const float4*)&ne[(size_t)n * H + lane * 4];
        *(float4*)&h[(size_t)n * H + lane * 4] = v;
        float s1 = v.x * a1.x + v.y * a1.y + v.z * a1.z + v.w * a1.w;
        float s2 = v.x * a2.x + v.y * a2.y + v.z * a2.z + v.w * a2.w;
#pragma unroll
        for (int off = 16; off; off >>= 1) {
            s1 += __shfl_xor_sync(0xffffffffu, s1, off);
            s2 += __shfl_xor_sync(0xffffffffu, s2, off);
        }
        if (lane == 0) { g_p1[n] = s1; g_p2[n] = s2; }
    }
}

// ---------------- per-level edge pass (CSR, no atomics) ----------------
__global__ __launch_bounds__(256) void k_edge(const float* __restrict__ h,
                                              const float* __restrict__ b_attn,
                                              int level) {
    int start = g_node_off[level], end = g_node_off[level + 1];
    int lane = threadIdx.x & 31;
    int warp = (blockIdx.x * blockDim.x + threadIdx.x) >> 5;
    int nwarp = (gridDim.x * blockDim.x) >> 5;
    float b = __ldg(b_attn);
    for (int i = start + warp; i < end; i += nwarp) {
        int d = g_node_list[i];
        int r0 = g_row[d], r1 = g_row[d + 1];
        if (r0 == r1) { if (lane == 0) g_denom[d] = 0.f; continue; }
        float p2d = g_p2[d];
        float denom = 0.f;
        float4 acc = make_float4(0.f, 0.f, 0.f, 0.f);
#pragma unroll 2
        for (int e = r0; e < r1; e++) {
            int src = __ldg(&g_es[e]);
            float ee = g_p1[src] + p2d + b;
            ee = ee > 0.f ? ee : 0.2f * ee;
            float ex = __expf(ee);
            denom += ex;
            float4 hv = __ldg((const float4*)(h + (size_t)src * H + lane * 4));
            acc.x += ex * hv.x; acc.y += ex * hv.y;
            acc.z += ex * hv.z; acc.w += ex * hv.w;
        }
        *(float4*)&g_agg[(size_t)d * H + lane * 4] = acc;
        if (lane == 0) g_denom[d] = denom;
    }
}

// ---------------- fp16 tensor-core GRU (mma.m16n8k16) ----------------
// block = 256 threads = 8 warps. warp: m0 = (warp&3)*16 nodes; nw64 = (warp>>2)*64 rows.
// D frag (f32): c0=(grp,2t4) c1=(grp,2t4+1) c2=(grp+8,2t4) c3=(grp+8,2t4+1)

__device__ __forceinline__ void issue_slab_h(const __half* __restrict__ W, int rowBase,
                                             int k0, __half* wsbuf, int t) {
#pragma unroll
    for (int p = 0; p < 2; p++) {
        int idx = t + p * 256;                 // 0..511
        int row = idx >> 2, seg = (idx & 3) << 3;   // 8 halves = 16B
        unsigned dst = (unsigned)__cvta_generic_to_shared(wsbuf + row * WSTH + seg);
        const __half* src = W + (size_t)(rowBase + row) * 128 + k0 + seg;
        asm volatile("cp.async.cg.shared.global [%0],[%1],16;"
                     :: "r"(dst), "l"(src) : "memory");
    }
}

__device__ __forceinline__ void mma_gemm_h(float (&d)[8][4], const __half* __restrict__ W,
                                           int rowBase, const __half* act,
                                           __half* ws0, __half* ws1,
                                           int m0, int nw64, int grp, int t4, int t) {
    __syncthreads();                       // prior consumers of ws done
    issue_slab_h(W, rowBase, 0, ws0, t);
    asm volatile("cp.async.commit_group;" ::: "memory");
    const unsigned* au = (const unsigned*)act;    // halves as u32 pairs
#pragma unroll
    for (int s = 0; s < 4; s++) {
        asm volatile("cp.async.wait_group 0;" ::: "memory");
        __syncthreads();
        if (s < 3) {
            issue_slab_h(W, rowBase, (s + 1) << 5, (s & 1) ? ws0 : ws1, t);
            asm volatile("cp.async.commit_group;" ::: "memory");
        }
        const unsigned* bu = (const unsigned*)((s & 1) ? ws1 : ws0);
#pragma unroll
        for (int kstep = 0; kstep < 2; kstep++) {
            // A frag: rows m0+grp / m0+grp+8, k pairs at (s*32 + kstep*16 + 2t4)(+8)
            int aw = (m0 + grp) * (ASTH / 2) + (s << 4) + (kstep << 3) + t4;
            unsigned a0 = au[aw];
            unsigned a1 = au[aw + 8 * (ASTH / 2)];
            unsigned a2 = au[aw + 4];
            unsigned a3 = au[aw + 4 + 8 * (ASTH / 2)];
#pragma unroll
            for (int f = 0; f < 8; f++) {
                int n = nw64 + (f << 3) + grp;
                int bw = n * (WSTH / 2) + (kstep << 3) + t4;
                unsigned b0 = bu[bw];
                unsigned b1 = bu[bw + 4];
                asm volatile(
                    "mma.sync.aligned.m16n8k16.row.col.f32.f16.f16.f32 "
                    "{%0,%1,%2,%3},{%4,%5,%6,%7},{%8,%9},{%0,%1,%2,%3};"
                    : "+f"(d[f][0]), "+f"(d[f][1]), "+f"(d[f][2]), "+f"(d[f][3])
                    : "r"(a0), "r"(a1), "r"(a2), "r"(a3), "r"(b0), "r"(b1));
            }
        }
    }
}

__global__ __launch_bounds__(256, 1) void k_gru(
    float* __restrict__ h, const float* __restrict__ node_type,
    const float* __restrict__ Wih, const float* __restrict__ bhh,
    const float* __restrict__ Wattn, int level) {
    extern __shared__ __align__(16) char smb[];
    __half* ws0  = (__half*)(smb + SMB_WS0);
    __half* ws1  = (__half*)(smb + SMB_WS1);
    __half* xs   = (__half*)(smb + SMB_XS);
    __half* hs   = (__half*)(smb + SMB_HS);
    float*  hsf  = (float*)(smb + SMB_HSF);
    float*  smnt = (float*)(smb + SMB_NT);
    float*  sbb  = (float*)(smb + SMB_BB);
    float*  sbh  = (float*)(smb + SMB_BH);
    float*  sp1  = (float*)(smb + SMB_SP1);
    float*  sp2  = (float*)(smb + SMB_SP2);
    int*    snode = (int*)(smb + SMB_SNODE);
    float*  sact  = (float*)(smb + SMB_SACT);
    float*  srd   = (float*)(smb + SMB_SRD);
    int*    stype = (int*)(smb + SMB_STYPE);

    int t = threadIdx.x;
    int start = g_node_off[level], end = g_node_off[level + 1];
    int cnt = end - start;
    int ntiles = (cnt + TILE_N - 1) / TILE_N;
    int lane = t & 31;
    int warp = t >> 5;
    int grp = lane >> 2;        // 0..7
    int t4 = lane & 3;          // 0..3
    int m0 = (warp & 3) << 4;   // node base within tile
    int nw64 = (warp >> 2) << 6; // row half: 0 or 64

    // stage constants once per block
    for (int idx = t; idx < 1152; idx += 256) {
        int c = idx % 3, r = idx / 3;
        smnt[c * 384 + r] = Wih[r * 131 + 128 + c];
    }
    for (int idx = t; idx < 384; idx += 256) {
        sbb[idx] = g_bbig[idx];
        sbh[idx] = bhh[idx];
    }

    for (int tile = blockIdx.x; tile < ntiles; tile += gridDim.x) {
        __syncthreads();          // constants ready / prior tile fully done
        if (t < TILE_N) {
            int slot = start + tile * TILE_N + t;
            int node = 0; float act = 0.f, rd = 0.f; int ty = 0;
            if (slot < end) {
                node = g_node_list[slot];
                float d = g_denom[node];
                if (d > 0.f) { act = 1.f; rd = 1.f / (d + 1e-16f); }
                float n1 = node_type[(size_t)node * 3 + 1];
                float n2 = node_type[(size_t)node * 3 + 2];
                ty = n1 > 0.5f ? 1 : (n2 > 0.5f ? 2 : 0);
            }
            snode[t] = node; sact[t] = act; srd[t] = rd; stype[t] = ty;
            sp1[t] = 0.f; sp2[t] = 0.f;
        }
        __syncthreads();
        // stage activations: xs = fp16(agg*rd), hs = fp16(h), hsf = fp32 h (node-major)
        for (int idx = t; idx < TILE_N * 32; idx += 256) {
            int n = idx & 63, j4 = idx >> 6;
            int node = snode[n];
            float rd = srd[n];
            float4 av = *(const float4*)&g_agg[(size_t)node * H + (j4 << 2)];
            float4 hv = *(const float4*)&h[(size_t)node * H + (j4 << 2)];
            int bh2 = n * ASTH + (j4 << 2);
            *(__half2*)&xs[bh2]     = __floats2half2_rn(av.x * rd, av.y * rd);
            *(__half2*)&xs[bh2 + 2] = __floats2half2_rn(av.z * rd, av.w * rd);
            *(__half2*)&hs[bh2]     = __floats2half2_rn(hv.x, hv.y);
            *(__half2*)&hs[bh2 + 2] = __floats2half2_rn(hv.z, hv.w);
            *(float4*)&hsf[n * ASTF + (j4 << 2)] = hv;
        }
        // (mma_gemm entry sync covers staging visibility)

        int ty_lo = 0, ty_hi = 0;
        float rr[8][4], zz[8][4];
        for (int chunk = 0; chunk < 3; chunk++) {
            float dx[8][4], dh[8][4];
#pragma unroll
            for (int f = 0; f < 8; f++)
#pragma unroll
                for (int j = 0; j < 4; j++) { dx[f][j] = 0.f; dh[f][j] = 0.f; }
            mma_gemm_h(dx, g_WbigH, chunk * H, xs, ws0, ws1, m0, nw64, grp, t4, t);
            mma_gemm_h(dh, g_WhhH,  chunk * H, hs, ws0, ws1, m0, nw64, grp, t4, t);
            if (chunk == 0) { ty_lo = stype[m0 + grp]; ty_hi = stype[m0 + grp + 8]; }
            int rb = chunk * H;
            if (chunk < 2) {
#pragma unroll
                for (int f = 0; f < 8; f++) {
                    int feat0 = nw64 + (f << 3) + (t4 << 1);
                    float bb0 = sbb[rb + feat0],  bb1 = sbb[rb + feat0 + 1];
                    float bh0 = sbh[rb + feat0],  bh1 = sbh[rb + feat0 + 1];
                    float clo0 = smnt[ty_lo * 384 + rb + feat0];
                    float clo1 = smnt[ty_lo * 384 + rb + feat0 + 1];
                    float chi0 = smnt[ty_hi * 384 + rb + feat0];
                    float chi1 = smnt[ty_hi * 384 + rb + feat0 + 1];
                    float g0 = sig_(dx[f][0] + bb0 + clo0 + dh[f][0] + bh0);
                    float g1 = sig_(dx[f][1] + bb1 + clo1 + dh[f][1] + bh1);
                    float g2 = sig_(dx[f][2] + bb0 + chi0 + dh[f][2] + bh0);
                    float g3 = sig_(dx[f][3] + bb1 + chi1 + dh[f][3] + bh1);
                    if (chunk == 0) { rr[f][0]=g0; rr[f][1]=g1; rr[f][2]=g2; rr[f][3]=g3; }
                    else            { zz[f][0]=g0; zz[f][1]=g1; zz[f][2]=g2; zz[f][3]=g3; }
                }
            } else {
                int nl_lo = m0 + grp, nl_hi = m0 + grp + 8;
                int node_lo = snode[nl_lo], node_hi = snode[nl_hi];
                bool act_lo = sact[nl_lo] > 0.f, act_hi = sact[nl_hi] > 0.f;
                float s1lo = 0.f, s2lo = 0.f, s1hi = 0.f, s2hi = 0.f;
#pragma unroll
                for (int f = 0; f < 8; f++) {
                    int feat0 = nw64 + (f << 3) + (t4 << 1);
                    float bb0 = sbb[rb + feat0],  bb1 = sbb[rb + feat0 + 1];
                    float bh0 = sbh[rb + feat0],  bh1 = sbh[rb + feat0 + 1];
                    float clo0 = smnt[ty_lo * 384 + rb + feat0];
                    float clo1 = smnt[ty_lo * 384 + rb + feat0 + 1];
                    float chi0 = smnt[ty_hi * 384 + rb + feat0];
                    float chi1 = smnt[ty_hi * 384 + rb + feat0 + 1];
                    float n0 = tanh_(dx[f][0] + bb0 + clo0 + rr[f][0] * (dh[f][0] + bh0));
                    float n1 = tanh_(dx[f][1] + bb1 + clo1 + rr[f][1] * (dh[f][1] + bh1));
                    float n2 = tanh_(dx[f][2] + bb0 + chi0 + rr[f][2] * (dh[f][2] + bh0));
                    float n3 = tanh_(dx[f][3] + bb1 + chi1 + rr[f][3] * (dh[f][3] + bh1));
                    float ho0 = hsf[nl_lo * ASTF + feat0];
                    float ho1 = hsf[nl_lo * ASTF + feat0 + 1];
                    float ho2 = hsf[nl_hi * ASTF + feat0];
                    float ho3 = hsf[nl_hi * ASTF + feat0 + 1];
                    float v0 = (1.f - zz[f][0]) * n0 + zz[f][0] * ho0;
                    float v1 = (1.f - zz[f][1]) * n1 + zz[f][1] * ho1;
                    float v2 = (1.f - zz[f][2]) * n2 + zz[f][2] * ho2;
                    float v3 = (1.f - zz[f][3]) * n3 + zz[f][3] * ho3;
                    if (act_lo)
                        *(float2*)&h[(size_t)node_lo * H + feat0] = make_float2(v0, v1);
                    if (act_hi)
                        *(float2*)&h[(size_t)node_hi * H + feat0] = make_float2(v2, v3);
                    float2 wa1 = *(const float2*)&Wattn[feat0];
                    float2 wa2 = *(const float2*)&Wattn[H + feat0];
                    s1lo += v0 * wa1.x + v1 * wa1.y;
                    s2lo += v0 * wa2.x + v1 * wa2.y;
                    s1hi += v2 * wa1.x + v3 * wa1.y;
                    s2hi += v2 * wa2.x + v3 * wa2.y;
                }
                atomicAdd(&sp1[nl_lo], s1lo);
                atomicAdd(&sp2[nl_lo], s2lo);
                atomicAdd(&sp1[nl_hi], s1hi);
                atomicAdd(&sp2[nl_hi], s2hi);
            }
        }
        __syncthreads();
        if (t < TILE_N && sact[t] > 0.f) {
            int node = snode[t];
            g_p1[node] = sp1[t];
            g_p2[node] = sp2[t];
        }
    }
}

// ---------------- launch ----------------
extern "C" void kernel_launch(void* const* d_in, const int* in_sizes, int n_in,
                              void* d_out, int out_size) {
    const float* node_embedding = (const float*)d_in[0];
    const float* node_type      = (const float*)d_in[1];
    const float* W_attn         = (const float*)d_in[2];
    const float* b_attn         = (const float*)d_in[3];
    const float* W_msg          = (const float*)d_in[4];
    const float* b_msg          = (const float*)d_in[5];
    const float* W_ih           = (const float*)d_in[6];
    const float* W_hh           = (const float*)d_in[7];
    const float* b_ih           = (const float*)d_in[8];
    const float* b_hh           = (const float*)d_in[9];
    const int*   edge_src       = (const int*)d_in[10];
    const int*   edge_dst       = (const int*)d_in[11];
    const int*   fnl            = (const int*)d_in[12];
    float* h = (float*)d_out;

    cudaFuncSetAttribute(k_gru, cudaFuncAttributeMaxDynamicSharedMemorySize, SMB_TOTAL);

    k_setup<<<384, 128>>>(W_ih, W_msg, b_ih, b_msg, W_hh);
    k_degcount<<<1563, 256>>>(fnl, edge_dst);
    k_scandeg<<<1, 1024>>>();
    k_scatter<<<1758, 256>>>(fnl, edge_src, edge_dst);
    k_init<<<6250, 256>>>(node_embedding, W_attn, h);

    for (int k = 1; k < DEPTH; k++) {
        k_edge<<<782, 256>>>(h, b_attn, k);
        k_gru<<<148, 256, SMB_TOTAL>>>(h, node_type, W_ih, b_hh, W_attn, k);
    }
}

// round 11
// speedup vs baseline: 1.4118x; 1.0231x over previous
#include <cuda_runtime.h>
#include <cuda_fp16.h>
#include <cstdint>

#define N_NODES 50000
#define N_EDGES 400000
#define H 128
#define DEPTH 8
#define TILE_N 64      // nodes per block tile
#define ASTH 136       // activation smem row stride in halves (128 + 8)
#define ASTF 132       // fp32 h epilogue stride (128 + 4)
#define WSTH 40        // weight slab row stride in halves (32 + 8)

// ---------------- device scratch (no allocation allowed) ----------------
__device__ float  g_agg[N_NODES * H];
__device__ float  g_denom[N_NODES];
__device__ float  g_p1[N_NODES];
__device__ float  g_p2[N_NODES];
__device__ int    g_node_list[N_NODES];
__device__ int    g_deg[N_NODES];
__device__ int    g_row[N_NODES + 1];
__device__ int    g_cur[N_NODES];
__device__ int    g_es[N_EDGES];          // edge srcs grouped by dst (CSR)
__device__ int    g_cnts[32];
__device__ int    g_node_off[DEPTH + 1];
// fused weights, ROW-major [384 rows][128 k], fp16
__device__ __half g_WbigH[384 * 128];     // W_ih[:,:128] @ W_msg
__device__ __half g_WhhH[384 * 128];
__device__ float  g_bbig[384];            // b_ih + W_ih[:,:128] @ b_msg

// smem byte offsets for k_gru dynamic smem
#define SMB_WSA0  0                 // 128*40 halves = 10240 B
#define SMB_WSA1  10240
#define SMB_WSB0  20480
#define SMB_WSB1  30720
#define SMB_XS    40960             // 64*136 halves = 17408 B
#define SMB_HS    58368             // 17408 B
#define SMB_HSF   75776             // 64*132 fp32 = 33792 B
#define SMB_NT    109568            // 3*384 fp32 = 4608 B
#define SMB_BB    114176            // 1536 B
#define SMB_BH    115712            // 1536 B
#define SMB_SP1   117248            // 256 B
#define SMB_SP2   117504
#define SMB_SNODE 117760
#define SMB_SACT  118016
#define SMB_SRD   118272
#define SMB_STYPE 118528
#define SMB_TOTAL 118784

__device__ __forceinline__ int clamp_lvl(int l) { return l < 0 ? 0 : (l > 7 ? 7 : l); }
__device__ __forceinline__ float sig_(float x) { return 1.0f / (1.0f + __expf(-x)); }
__device__ __forceinline__ float tanh_(float x) { return 2.0f / (1.0f + __expf(-2.0f * x)) - 1.0f; }

// ---------------- setup: fuse W_big + convert Whh + zero deg/cnts ----------------
__global__ __launch_bounds__(128) void k_setup(const float* __restrict__ Wih,
                                               const float* __restrict__ Wmsg,
                                               const float* __restrict__ bih,
                                               const float* __restrict__ bmsg,
                                               const float* __restrict__ Whh) {
    int r = blockIdx.x;        // 0..383
    int m = threadIdx.x;       // 0..127
    __shared__ float wr[128];
    wr[m] = Wih[r * 131 + m];
    __syncthreads();
    float s = 0.f;
#pragma unroll 8
    for (int j = 0; j < 128; j++) s += wr[j] * Wmsg[j * 128 + m];
    g_WbigH[r * 128 + m] = __float2half(s);
    if (m == 0) {
        float b = bih[r];
        for (int j = 0; j < 128; j++) b += wr[j] * bmsg[j];
        g_bbig[r] = b;
    }
    int gid = r * 128 + m;                       // 0..49151
    g_WhhH[gid] = __float2half(Whh[gid]);        // exactly 384*128 elements
    for (int idx = gid; idx < N_NODES; idx += 384 * 128) g_deg[idx] = 0;
    if (gid < 32) g_cnts[gid] = 0;
}

__global__ __launch_bounds__(256) void k_degcount(const int* __restrict__ fnl,
                                                  const int* __restrict__ edst) {
    __shared__ int sc[8];
    int t = threadIdx.x;
    if (t < 8) sc[t] = 0;
    __syncthreads();
    int idx = blockIdx.x * blockDim.x + t;
    int stride = gridDim.x * blockDim.x;
    for (int i = idx; i < N_EDGES; i += stride)
        atomicAdd(&g_deg[__ldg(&edst[i])], 1);
    for (int i = idx; i < N_NODES; i += stride)
        atomicAdd(&sc[clamp_lvl(__ldg(&fnl[i]))], 1);
    __syncthreads();
    if (t < 8 && sc[t] > 0) atomicAdd(&g_cnts[t], sc[t]);
}

// level scan (thread 0) + exclusive degree scan -> g_row/g_cur (1024 threads)
#define SCAN_PER 49
__global__ __launch_bounds__(1024) void k_scandeg() {
    __shared__ int wsum[32];
    int t = threadIdx.x;
    if (t == 0) {
        int no = 0;
        for (int l = 0; l < 8; l++) { g_node_off[l] = no; no += g_cnts[l]; }
        g_node_off[8] = no;
        for (int l = 0; l < 8; l++) g_cnts[16 + l] = g_node_off[l];
    }
    int base = t * SCAN_PER;
    int s = 0;
    for (int j = 0; j < SCAN_PER; j++) {
        int idx = base + j;
        if (idx < N_NODES) s += g_deg[idx];
    }
    int lane = t & 31, w = t >> 5;
    int v = s;
#pragma unroll
    for (int off = 1; off < 32; off <<= 1) {
        int n = __shfl_up_sync(0xffffffffu, v, off);
        if (lane >= off) v += n;
    }
    if (lane == 31) wsum[w] = v;
    __syncthreads();
    if (w == 0) {
        int wv = wsum[lane];
#pragma unroll
        for (int off = 1; off < 32; off <<= 1) {
            int n = __shfl_up_sync(0xffffffffu, wv, off);
            if (lane >= off) wv += n;
        }
        wsum[lane] = wv;
    }
    __syncthreads();
    int run = v - s + (w > 0 ? wsum[w - 1] : 0);
    for (int j = 0; j < SCAN_PER; j++) {
        int idx = base + j;
        if (idx < N_NODES) {
            g_row[idx] = run;
            g_cur[idx] = run;
            run += g_deg[idx];
        }
    }
    if (t == 1023) g_row[N_NODES] = run;
}

// node scatter (by level) + edge scatter (CSR fill), one kernel
__global__ __launch_bounds__(256) void k_scatter(const int* __restrict__ fnl,
                                                 const int* __restrict__ esrc,
                                                 const int* __restrict__ edst) {
    __shared__ int scnt[8];
    __shared__ int sbase[8];
    int t = threadIdx.x;
    if (t < 8) scnt[t] = 0;
    __syncthreads();
    int i = blockIdx.x * blockDim.x + t;
    int key = -1, lp = 0;
    if (i < N_NODES) {
        key = clamp_lvl(__ldg(&fnl[i]));
        lp = atomicAdd(&scnt[key], 1);
    } else if (i < N_NODES + N_EDGES) {
        int e = i - N_NODES;
        int d = __ldg(&edst[e]);
        int pos = atomicAdd(&g_cur[d], 1);
        g_es[pos] = __ldg(&esrc[e]);
    }
    __syncthreads();
    if (t < 8 && scnt[t] > 0) sbase[t] = atomicAdd(&g_cnts[16 + t], scnt[t]);
    __syncthreads();
    if (key >= 0) g_node_list[sbase[key] + lp] = i;
}

__global__ __launch_bounds__(256) void k_init(const float* __restrict__ ne,
                                              const float* __restrict__ wa,
                                              float* __restrict__ h) {
    int lane = threadIdx.x & 31;
    int w = (blockIdx.x * blockDim.x + threadIdx.x) >> 5;
    int nw = (gridDim.x * blockDim.x) >> 5;
    float4 a1 = *(const float4*)&wa[lane * 4];
    float4 a2 = *(const float4*)&wa[H + lane * 4];
    for (int n = w; n < N_NODES; n += nw) {
        float4 v = *(const float4*)&ne[(size_t)n * H + lane * 4];
        *(float4*)&h[(size_t)n * H + lane * 4] = v;
        float s1 = v.x * a1.x + v.y * a1.y + v.z * a1.z + v.w * a1.w;
        float s2 = v.x * a2.x + v.y * a2.y + v.z * a2.z + v.w * a2.w;
#pragma unroll
        for (int off = 16; off; off >>= 1) {
            s1 += __shfl_xor_sync(0xffffffffu, s1, off);
            s2 += __shfl_xor_sync(0xffffffffu, s2, off);
        }
        if (lane == 0) { g_p1[n] = s1; g_p2[n] = s2; }
    }
}

// ---------------- per-level edge pass (CSR, no atomics) ----------------
__global__ __launch_bounds__(256) void k_edge(const float* __restrict__ h,
                                              const float* __restrict__ b_attn,
                                              int level) {
    int start = g_node_off[level], end = g_node_off[level + 1];
    int lane = threadIdx.x & 31;
    int warp = (blockIdx.x * blockDim.x + threadIdx.x) >> 5;
    int nwarp = (gridDim.x * blockDim.x) >> 5;
    float b = __ldg(b_attn);
    for (int i = start + warp; i < end; i += nwarp) {
        int d = g_node_list[i];
        int r0 = g_row[d], r1 = g_row[d + 1];
        if (r0 == r1) { if (lane == 0) g_denom[d] = 0.f; continue; }
        float p2d = g_p2[d];
        float denom = 0.f;
        float4 acc = make_float4(0.f, 0.f, 0.f, 0.f);
#pragma unroll 2
        for (int e = r0; e < r1; e++) {
            int src = __ldg(&g_es[e]);
            float ee = g_p1[src] + p2d + b;
            ee = ee > 0.f ? ee : 0.2f * ee;
            float ex = __expf(ee);
            denom += ex;
            float4 hv = __ldg((const float4*)(h + (size_t)src * H + lane * 4));
            acc.x += ex * hv.x; acc.y += ex * hv.y;
            acc.z += ex * hv.z; acc.w += ex * hv.w;
        }
        *(float4*)&g_agg[(size_t)d * H + lane * 4] = acc;
        if (lane == 0) g_denom[d] = denom;
    }
}

// ---------------- fp16 tensor-core GRU (mma.m16n8k16, dual-stream pipelined) ------
// block = 256 threads = 8 warps. warp: m0 = (warp&3)*16 nodes; nw64 = (warp>>2)*64 rows.
// D frag (f32): c0=(grp,2t4) c1=(grp,2t4+1) c2=(grp+8,2t4) c3=(grp+8,2t4+1)

__device__ __forceinline__ void issue_dual(int rowBase, int k0,
                                           __half* bufA, __half* bufB, int t) {
#pragma unroll
    for (int p = 0; p < 2; p++) {
        int idx = t + p * 256;                 // 0..511
        int row = idx >> 2, seg = (idx & 3) << 3;   // 8 halves = 16B
        unsigned da = (unsigned)__cvta_generic_to_shared(bufA + row * WSTH + seg);
        const __half* sa = g_WbigH + (size_t)(rowBase + row) * 128 + k0 + seg;
        asm volatile("cp.async.cg.shared.global [%0],[%1],16;"
                     :: "r"(da), "l"(sa) : "memory");
        unsigned db = (unsigned)__cvta_generic_to_shared(bufB + row * WSTH + seg);
        const __half* sb = g_WhhH + (size_t)(rowBase + row) * 128 + k0 + seg;
        asm volatile("cp.async.cg.shared.global [%0],[%1],16;"
                     :: "r"(db), "l"(sb) : "memory");
    }
}

// computes dx += Wbig-chunk @ xs^T and dh += Whh-chunk @ hs^T, properly pipelined:
// per slab s: wait(s) -> sync -> issue(s+1) -> compute(s)  [fetch s+1 overlaps compute s]
__device__ __forceinline__ void mma_dual(float (&dx)[8][4], float (&dh)[8][4],
                                         int rowBase,
                                         const __half* xs, const __half* hs,
                                         __half* wsA0, __half* wsA1,
                                         __half* wsB0, __half* wsB1,
                                         int m0, int nw64, int grp, int t4, int t) {
    __syncthreads();                       // prior consumers of buffers / staging done
    issue_dual(rowBase, 0, wsA0, wsB0, t);
    asm volatile("cp.async.commit_group;" ::: "memory");
    const unsigned* xu = (const unsigned*)xs;
    const unsigned* hu = (const unsigned*)hs;
#pragma unroll
    for (int s = 0; s < 4; s++) {
        asm volatile("cp.async.wait_group 0;" ::: "memory");   // slab s arrived
        __syncthreads();                    // copies visible + compute(s-1) done by all
        if (s < 3) {
            issue_dual(rowBase, (s + 1) << 5,
                       (s & 1) ? wsA0 : wsA1, (s & 1) ? wsB0 : wsB1, t);
            asm volatile("cp.async.commit_group;" ::: "memory");
        }
        const unsigned* ba = (const unsigned*)((s & 1) ? wsA1 : wsA0);
        const unsigned* bb = (const unsigned*)((s & 1) ? wsB1 : wsB0);
#pragma unroll
        for (int kstep = 0; kstep < 2; kstep++) {
            int aw = (m0 + grp) * (ASTH / 2) + (s << 4) + (kstep << 3) + t4;
            unsigned xa0 = xu[aw];
            unsigned xa1 = xu[aw + 8 * (ASTH / 2)];
            unsigned xa2 = xu[aw + 4];
            unsigned xa3 = xu[aw + 4 + 8 * (ASTH / 2)];
            unsigned ha0 = hu[aw];
            unsigned ha1 = hu[aw + 8 * (ASTH / 2)];
            unsigned ha2 = hu[aw + 4];
            unsigned ha3 = hu[aw + 4 + 8 * (ASTH / 2)];
#pragma unroll
            for (int f = 0; f < 8; f++) {
                int bw = (nw64 + (f << 3) + grp) * (WSTH / 2) + (kstep << 3) + t4;
                unsigned b0 = ba[bw];
                unsigned b1 = ba[bw + 4];
                asm volatile(
                    "mma.sync.aligned.m16n8k16.row.col.f32.f16.f16.f32 "
                    "{%0,%1,%2,%3},{%4,%5,%6,%7},{%8,%9},{%0,%1,%2,%3};"
                    : "+f"(dx[f][0]), "+f"(dx[f][1]), "+f"(dx[f][2]), "+f"(dx[f][3])
                    : "r"(xa0), "r"(xa1), "r"(xa2), "r"(xa3), "r"(b0), "r"(b1));
                unsigned c0 = bb[bw];
                unsigned c1 = bb[bw + 4];
                asm volatile(
                    "mma.sync.aligned.m16n8k16.row.col.f32.f16.f16.f32 "
                    "{%0,%1,%2,%3},{%4,%5,%6,%7},{%8,%9},{%0,%1,%2,%3};"
                    : "+f"(dh[f][0]), "+f"(dh[f][1]), "+f"(dh[f][2]), "+f"(dh[f][3])
                    : "r"(ha0), "r"(ha1), "r"(ha2), "r"(ha3), "r"(c0), "r"(c1));
            }
        }
    }
}

__global__ __launch_bounds__(256, 1) void k_gru(
    float* __restrict__ h, const float* __restrict__ node_type,
    const float* __restrict__ Wih, const float* __restrict__ bhh,
    const float* __restrict__ Wattn, int level) {
    extern __shared__ __align__(16) char smb[];
    __half* wsA0 = (__half*)(smb + SMB_WSA0);
    __half* wsA1 = (__half*)(smb + SMB_WSA1);
    __half* wsB0 = (__half*)(smb + SMB_WSB0);
    __half* wsB1 = (__half*)(smb + SMB_WSB1);
    __half* xs   = (__half*)(smb + SMB_XS);
    __half* hs   = (__half*)(smb + SMB_HS);
    float*  hsf  = (float*)(smb + SMB_HSF);
    float*  smnt = (float*)(smb + SMB_NT);
    float*  sbb  = (float*)(smb + SMB_BB);
    float*  sbh  = (float*)(smb + SMB_BH);
    float*  sp1  = (float*)(smb + SMB_SP1);
    float*  sp2  = (float*)(smb + SMB_SP2);
    int*    snode = (int*)(smb + SMB_SNODE);
    float*  sact  = (float*)(smb + SMB_SACT);
    float*  srd   = (float*)(smb + SMB_SRD);
    int*    stype = (int*)(smb + SMB_STYPE);

    int t = threadIdx.x;
    int start = g_node_off[level], end = g_node_off[level + 1];
    int cnt = end - start;
    int ntiles = (cnt + TILE_N - 1) / TILE_N;
    int lane = t & 31;
    int warp = t >> 5;
    int grp = lane >> 2;        // 0..7
    int t4 = lane & 3;          // 0..3
    int m0 = (warp & 3) << 4;   // node base within tile
    int nw64 = (warp >> 2) << 6; // row half: 0 or 64

    // stage constants once per block
    for (int idx = t; idx < 1152; idx += 256) {
        int c = idx % 3, r = idx / 3;
        smnt[c * 384 + r] = Wih[r * 131 + 128 + c];
    }
    for (int idx = t; idx < 384; idx += 256) {
        sbb[idx] = g_bbig[idx];
        sbh[idx] = bhh[idx];
    }

    for (int tile = blockIdx.x; tile < ntiles; tile += gridDim.x) {
        __syncthreads();          // constants ready / prior tile fully done
        if (t < TILE_N) {
            int slot = start + tile * TILE_N + t;
            int node = 0; float act = 0.f, rd = 0.f; int ty = 0;
            if (slot < end) {
                node = g_node_list[slot];
                float d = g_denom[node];
                if (d > 0.f) { act = 1.f; rd = 1.f / (d + 1e-16f); }
                float n1 = node_type[(size_t)node * 3 + 1];
                float n2 = node_type[(size_t)node * 3 + 2];
                ty = n1 > 0.5f ? 1 : (n2 > 0.5f ? 2 : 0);
            }
            snode[t] = node; sact[t] = act; srd[t] = rd; stype[t] = ty;
            sp1[t] = 0.f; sp2[t] = 0.f;
        }
        __syncthreads();
        // stage activations: xs = fp16(agg*rd), hs = fp16(h), hsf = fp32 h (node-major)
        for (int idx = t; idx < TILE_N * 32; idx += 256) {
            int n = idx & 63, j4 = idx >> 6;
            int node = snode[n];
            float rd = srd[n];
            float4 av = *(const float4*)&g_agg[(size_t)node * H + (j4 << 2)];
            float4 hv = *(const float4*)&h[(size_t)node * H + (j4 << 2)];
            int bh2 = n * ASTH + (j4 << 2);
            *(__half2*)&xs[bh2]     = __floats2half2_rn(av.x * rd, av.y * rd);
            *(__half2*)&xs[bh2 + 2] = __floats2half2_rn(av.z * rd, av.w * rd);
            *(__half2*)&hs[bh2]     = __floats2half2_rn(hv.x, hv.y);
            *(__half2*)&hs[bh2 + 2] = __floats2half2_rn(hv.z, hv.w);
            *(float4*)&hsf[n * ASTF + (j4 << 2)] = hv;
        }
        // (mma_dual entry sync covers staging visibility)

        int ty_lo = 0, ty_hi = 0;
        float rr[8][4], zz[8][4];
        for (int chunk = 0; chunk < 3; chunk++) {
            float dx[8][4], dh[8][4];
#pragma unroll
            for (int f = 0; f < 8; f++)
#pragma unroll
                for (int j = 0; j < 4; j++) { dx[f][j] = 0.f; dh[f][j] = 0.f; }
            mma_dual(dx, dh, chunk * H, xs, hs, wsA0, wsA1, wsB0, wsB1,
                     m0, nw64, grp, t4, t);
            if (chunk == 0) { ty_lo = stype[m0 + grp]; ty_hi = stype[m0 + grp + 8]; }
            int rb = chunk * H;
            if (chunk < 2) {
#pragma unroll
                for (int f = 0; f < 8; f++) {
                    int feat0 = nw64 + (f << 3) + (t4 << 1);
                    float bb0 = sbb[rb + feat0],  bb1 = sbb[rb + feat0 + 1];
                    float bh0 = sbh[rb + feat0],  bh1 = sbh[rb + feat0 + 1];
                    float clo0 = smnt[ty_lo * 384 + rb + feat0];
                    float clo1 = smnt[ty_lo * 384 + rb + feat0 + 1];
                    float chi0 = smnt[ty_hi * 384 + rb + feat0];
                    float chi1 = smnt[ty_hi * 384 + rb + feat0 + 1];
                    float g0 = sig_(dx[f][0] + bb0 + clo0 + dh[f][0] + bh0);
                    float g1 = sig_(dx[f][1] + bb1 + clo1 + dh[f][1] + bh1);
                    float g2 = sig_(dx[f][2] + bb0 + chi0 + dh[f][2] + bh0);
                    float g3 = sig_(dx[f][3] + bb1 + chi1 + dh[f][3] + bh1);
                    if (chunk == 0) { rr[f][0]=g0; rr[f][1]=g1; rr[f][2]=g2; rr[f][3]=g3; }
                    else            { zz[f][0]=g0; zz[f][1]=g1; zz[f][2]=g2; zz[f][3]=g3; }
                }
            } else {
                int nl_lo = m0 + grp, nl_hi = m0 + grp + 8;
                int node_lo = snode[nl_lo], node_hi = snode[nl_hi];
                bool act_lo = sact[nl_lo] > 0.f, act_hi = sact[nl_hi] > 0.f;
                float s1lo = 0.f, s2lo = 0.f, s1hi = 0.f, s2hi = 0.f;
#pragma unroll
                for (int f = 0; f < 8; f++) {
                    int feat0 = nw64 + (f << 3) + (t4 << 1);
                    float bb0 = sbb[rb + feat0],  bb1 = sbb[rb + feat0 + 1];
                    float bh0 = sbh[rb + feat0],  bh1 = sbh[rb + feat0 + 1];
                    float clo0 = smnt[ty_lo * 384 + rb + feat0];
                    float clo1 = smnt[ty_lo * 384 + rb + feat0 + 1];
                    float chi0 = smnt[ty_hi * 384 + rb + feat0];
                    float chi1 = smnt[ty_hi * 384 + rb + feat0 + 1];
                    float n0 = tanh_(dx[f][0] + bb0 + clo0 + rr[f][0] * (dh[f][0] + bh0));
                    float n1 = tanh_(dx[f][1] + bb1 + clo1 + rr[f][1] * (dh[f][1] + bh1));
                    float n2 = tanh_(dx[f][2] + bb0 + chi0 + rr[f][2] * (dh[f][2] + bh0));
                    float n3 = tanh_(dx[f][3] + bb1 + chi1 + rr[f][3] * (dh[f][3] + bh1));
                    float ho0 = hsf[nl_lo * ASTF + feat0];
                    float ho1 = hsf[nl_lo * ASTF + feat0 + 1];
                    float ho2 = hsf[nl_hi * ASTF + feat0];
                    float ho3 = hsf[nl_hi * ASTF + feat0 + 1];
                    float v0 = (1.f - zz[f][0]) * n0 + zz[f][0] * ho0;
                    float v1 = (1.f - zz[f][1]) * n1 + zz[f][1] * ho1;
                    float v2 = (1.f - zz[f][2]) * n2 + zz[f][2] * ho2;
                    float v3 = (1.f - zz[f][3]) * n3 + zz[f][3] * ho3;
                    if (act_lo)
                        *(float2*)&h[(size_t)node_lo * H + feat0] = make_float2(v0, v1);
                    if (act_hi)
                        *(float2*)&h[(size_t)node_hi * H + feat0] = make_float2(v2, v3);
                    float2 wa1 = *(const float2*)&Wattn[feat0];
                    float2 wa2 = *(const float2*)&Wattn[H + feat0];
                    s1lo += v0 * wa1.x + v1 * wa1.y;
                    s2lo += v0 * wa2.x + v1 * wa2.y;
                    s1hi += v2 * wa1.x + v3 * wa1.y;
                    s2hi += v2 * wa2.x + v3 * wa2.y;
                }
                atomicAdd(&sp1[nl_lo], s1lo);
                atomicAdd(&sp2[nl_lo], s2lo);
                atomicAdd(&sp1[nl_hi], s1hi);
                atomicAdd(&sp2[nl_hi], s2hi);
            }
        }
        __syncthreads();
        if (t < TILE_N && sact[t] > 0.f) {
            int node = snode[t];
            g_p1[node] = sp1[t];
            g_p2[node] = sp2[t];
        }
    }
}

// ---------------- launch ----------------
extern "C" void kernel_launch(void* const* d_in, const int* in_sizes, int n_in,
                              void* d_out, int out_size) {
    const float* node_embedding = (const float*)d_in[0];
    const float* node_type      = (const float*)d_in[1];
    const float* W_attn         = (const float*)d_in[2];
    const float* b_attn         = (const float*)d_in[3];
    const float* W_msg          = (const float*)d_in[4];
    const float* b_msg          = (const float*)d_in[5];
    const float* W_ih           = (const float*)d_in[6];
    const float* W_hh           = (const float*)d_in[7];
    const float* b_ih           = (const float*)d_in[8];
    const float* b_hh           = (const float*)d_in[9];
    const int*   edge_src       = (const int*)d_in[10];
    const int*   edge_dst       = (const int*)d_in[11];
    const int*   fnl            = (const int*)d_in[12];
    float* h = (float*)d_out;

    cudaFuncSetAttribute(k_gru, cudaFuncAttributeMaxDynamicSharedMemorySize, SMB_TOTAL);

    k_setup<<<384, 128>>>(W_ih, W_msg, b_ih, b_msg, W_hh);
    k_degcount<<<1563, 256>>>(fnl, edge_dst);
    k_scandeg<<<1, 1024>>>();
    k_scatter<<<1758, 256>>>(fnl, edge_src, edge_dst);
    k_init<<<6250, 256>>>(node_embedding, W_attn, h);

    for (int k = 1; k < DEPTH; k++) {
        k_edge<<<782, 256>>>(h, b_attn, k);
        k_gru<<<148, 256, SMB_TOTAL>>>(h, node_type, W_ih, b_hh, W_attn, k);
    }
}

// round 12
// speedup vs baseline: 1.5665x; 1.1095x over previous
#include <cuda_runtime.h>
#include <cuda_fp16.h>
#include <cstdint>

#define N_NODES 50000
#define N_EDGES 400000
#define H 128
#define DEPTH 8
#define TILE_N 64      // nodes per block tile
#define NTHREADS 512
#define ASTH 136       // activation smem row stride in halves (128 + 8)
#define ASTF 132       // fp32 h epilogue stride (128 + 4)
#define WSTH 40        // weight slab row stride in halves (32 + 8)

// ---------------- device scratch (no allocation allowed) ----------------
__device__ float  g_p1[N_NODES];
__device__ float  g_p2[N_NODES];
__device__ int    g_node_list[N_NODES];
__device__ int    g_deg[N_NODES];
__device__ int    g_row[N_NODES + 1];
__device__ int    g_cur[N_NODES];
__device__ int    g_es[N_EDGES];          // edge srcs grouped by dst (CSR)
__device__ int    g_cnts[32];
__device__ int    g_node_off[DEPTH + 1];
// fused weights, ROW-major [384 rows][128 k], fp16
__device__ __half g_WbigH[384 * 128];     // W_ih[:,:128] @ W_msg
__device__ __half g_WhhH[384 * 128];
__device__ float  g_bbig[384];            // b_ih + W_ih[:,:128] @ b_msg

// smem byte offsets for k_gru dynamic smem
#define SMB_WSA0  0                 // 128*40 halves = 10240 B
#define SMB_WSA1  10240
#define SMB_WSB0  20480
#define SMB_WSB1  30720
#define SMB_XS    40960             // 64*136 halves = 17408 B
#define SMB_HS    58368             // 17408 B
#define SMB_HSF   75776             // 64*132 fp32 = 33792 B
#define SMB_NT    109568            // 3*384 fp32 = 4608 B
#define SMB_BB    114176            // 1536 B
#define SMB_BH    115712            // 1536 B
#define SMB_SP1   117248            // 256 B
#define SMB_SP2   117504
#define SMB_SNODE 117760
#define SMB_SACT  118016
#define SMB_SRD   118272
#define SMB_STYPE 118528
#define SMB_TOTAL 118784

__device__ __forceinline__ int clamp_lvl(int l) { return l < 0 ? 0 : (l > 7 ? 7 : l); }
__device__ __forceinline__ float sig_(float x) { return 1.0f / (1.0f + __expf(-x)); }
__device__ __forceinline__ float tanh_(float x) { return 2.0f / (1.0f + __expf(-2.0f * x)) - 1.0f; }

// ---------------- setup: fuse W_big + convert Whh + zero deg/cnts ----------------
__global__ __launch_bounds__(128) void k_setup(const float* __restrict__ Wih,
                                               const float* __restrict__ Wmsg,
                                               const float* __restrict__ bih,
                                               const float* __restrict__ bmsg,
                                               const float* __restrict__ Whh) {
    int r = blockIdx.x;        // 0..383
    int m = threadIdx.x;       // 0..127
    __shared__ float wr[128];
    wr[m] = Wih[r * 131 + m];
    __syncthreads();
    float s = 0.f;
#pragma unroll 8
    for (int j = 0; j < 128; j++) s += wr[j] * Wmsg[j * 128 + m];
    g_WbigH[r * 128 + m] = __float2half(s);
    if (m == 0) {
        float b = bih[r];
        for (int j = 0; j < 128; j++) b += wr[j] * bmsg[j];
        g_bbig[r] = b;
    }
    int gid = r * 128 + m;                       // 0..49151
    g_WhhH[gid] = __float2half(Whh[gid]);        // exactly 384*128 elements
    for (int idx = gid; idx < N_NODES; idx += 384 * 128) g_deg[idx] = 0;
    if (gid < 32) g_cnts[gid] = 0;
}

__global__ __launch_bounds__(256) void k_degcount(const int* __restrict__ fnl,
                                                  const int* __restrict__ edst) {
    __shared__ int sc[8];
    int t = threadIdx.x;
    if (t < 8) sc[t] = 0;
    __syncthreads();
    int idx = blockIdx.x * blockDim.x + t;
    int stride = gridDim.x * blockDim.x;
    for (int i = idx; i < N_EDGES; i += stride)
        atomicAdd(&g_deg[__ldg(&edst[i])], 1);
    for (int i = idx; i < N_NODES; i += stride)
        atomicAdd(&sc[clamp_lvl(__ldg(&fnl[i]))], 1);
    __syncthreads();
    if (t < 8 && sc[t] > 0) atomicAdd(&g_cnts[t], sc[t]);
}

// level scan (thread 0) + exclusive degree scan -> g_row/g_cur (1024 threads)
#define SCAN_PER 49
__global__ __launch_bounds__(1024) void k_scandeg() {
    __shared__ int wsum[32];
    int t = threadIdx.x;
    if (t == 0) {
        int no = 0;
        for (int l = 0; l < 8; l++) { g_node_off[l] = no; no += g_cnts[l]; }
        g_node_off[8] = no;
        for (int l = 0; l < 8; l++) g_cnts[16 + l] = g_node_off[l];
    }
    int base = t * SCAN_PER;
    int s = 0;
    for (int j = 0; j < SCAN_PER; j++) {
        int idx = base + j;
        if (idx < N_NODES) s += g_deg[idx];
    }
    int lane = t & 31, w = t >> 5;
    int v = s;
#pragma unroll
    for (int off = 1; off < 32; off <<= 1) {
        int n = __shfl_up_sync(0xffffffffu, v, off);
        if (lane >= off) v += n;
    }
    if (lane == 31) wsum[w] = v;
    __syncthreads();
    if (w == 0) {
        int wv = wsum[lane];
#pragma unroll
        for (int off = 1; off < 32; off <<= 1) {
            int n = __shfl_up_sync(0xffffffffu, wv, off);
            if (lane >= off) wv += n;
        }
        wsum[lane] = wv;
    }
    __syncthreads();
    int run = v - s + (w > 0 ? wsum[w - 1] : 0);
    for (int j = 0; j < SCAN_PER; j++) {
        int idx = base + j;
        if (idx < N_NODES) {
            g_row[idx] = run;
            g_cur[idx] = run;
            run += g_deg[idx];
        }
    }
    if (t == 1023) g_row[N_NODES] = run;
}

// node scatter (by level) + edge scatter (CSR fill), one kernel
__global__ __launch_bounds__(256) void k_scatter(const int* __restrict__ fnl,
                                                 const int* __restrict__ esrc,
                                                 const int* __restrict__ edst) {
    __shared__ int scnt[8];
    __shared__ int sbase[8];
    int t = threadIdx.x;
    if (t < 8) scnt[t] = 0;
    __syncthreads();
    int i = blockIdx.x * blockDim.x + t;
    int key = -1, lp = 0;
    if (i < N_NODES) {
        key = clamp_lvl(__ldg(&fnl[i]));
        lp = atomicAdd(&scnt[key], 1);
    } else if (i < N_NODES + N_EDGES) {
        int e = i - N_NODES;
        int d = __ldg(&edst[e]);
        int pos = atomicAdd(&g_cur[d], 1);
        g_es[pos] = __ldg(&esrc[e]);
    }
    __syncthreads();
    if (t < 8 && scnt[t] > 0) sbase[t] = atomicAdd(&g_cnts[16 + t], scnt[t]);
    __syncthreads();
    if (key >= 0) g_node_list[sbase[key] + lp] = i;
}

__global__ __launch_bounds__(256) void k_init(const float* __restrict__ ne,
                                              const float* __restrict__ wa,
                                              float* __restrict__ h) {
    int lane = threadIdx.x & 31;
    int w = (blockIdx.x * blockDim.x + threadIdx.x) >> 5;
    int nw = (gridDim.x * blockDim.x) >> 5;
    float4 a1 = *(const float4*)&wa[lane * 4];
    float4 a2 = *(const float4*)&wa[H + lane * 4];
    for (int n = w; n < N_NODES; n += nw) {
        float4 v = *(const float4*)&ne[(size_t)n * H + lane * 4];
        *(float4*)&h[(size_t)n * H + lane * 4] = v;
        float s1 = v.x * a1.x + v.y * a1.y + v.z * a1.z + v.w * a1.w;
        float s2 = v.x * a2.x + v.y * a2.y + v.z * a2.z + v.w * a2.w;
#pragma unroll
        for (int off = 16; off; off >>= 1) {
            s1 += __shfl_xor_sync(0xffffffffu, s1, off);
            s2 += __shfl_xor_sync(0xffffffffu, s2, off);
        }
        if (lane == 0) { g_p1[n] = s1; g_p2[n] = s2; }
    }
}

// ---------------- fused edge + fp16 tensor-core GRU ----------------
// block = 512 threads = 16 warps. warp: m0 = (warp&3)*16 nodes; nw32 = (warp>>2)*32 rows.
// D frag (f32): c0=(grp,2t4) c1=(grp,2t4+1) c2=(grp+8,2t4) c3=(grp+8,2t4+1)

__device__ __forceinline__ void issue_dual(int rowBase, int k0,
                                           __half* bufA, __half* bufB, int t) {
    int row = t >> 2, seg = (t & 3) << 3;       // 512 threads cover 128 rows x 4 segs
    unsigned da = (unsigned)__cvta_generic_to_shared(bufA + row * WSTH + seg);
    const __half* sa = g_WbigH + (size_t)(rowBase + row) * 128 + k0 + seg;
    asm volatile("cp.async.cg.shared.global [%0],[%1],16;"
                 :: "r"(da), "l"(sa) : "memory");
    unsigned db = (unsigned)__cvta_generic_to_shared(bufB + row * WSTH + seg);
    const __half* sb = g_WhhH + (size_t)(rowBase + row) * 128 + k0 + seg;
    asm volatile("cp.async.cg.shared.global [%0],[%1],16;"
                 :: "r"(db), "l"(sb) : "memory");
}

// dx += Wbig-chunk @ xs^T and dh += Whh-chunk @ hs^T, pipelined:
// per slab s: wait(s) -> sync -> issue(s+1) -> compute(s)
__device__ __forceinline__ void mma_dual(float (&dx)[4][4], float (&dh)[4][4],
                                         int rowBase,
                                         const __half* xs, const __half* hs,
                                         __half* wsA0, __half* wsA1,
                                         __half* wsB0, __half* wsB1,
                                         int m0, int nw32, int grp, int t4, int t) {
    __syncthreads();                       // prior consumers of buffers / staging done
    issue_dual(rowBase, 0, wsA0, wsB0, t);
    asm volatile("cp.async.commit_group;" ::: "memory");
    const unsigned* xu = (const unsigned*)xs;
    const unsigned* hu = (const unsigned*)hs;
#pragma unroll
    for (int s = 0; s < 4; s++) {
        asm volatile("cp.async.wait_group 0;" ::: "memory");   // slab s arrived
        __syncthreads();                    // copies visible + compute(s-1) done by all
        if (s < 3) {
            issue_dual(rowBase, (s + 1) << 5,
                       (s & 1) ? wsA0 : wsA1, (s & 1) ? wsB0 : wsB1, t);
            asm volatile("cp.async.commit_group;" ::: "memory");
        }
        const unsigned* ba = (const unsigned*)((s & 1) ? wsA1 : wsA0);
        const unsigned* bb = (const unsigned*)((s & 1) ? wsB1 : wsB0);
#pragma unroll
        for (int kstep = 0; kstep < 2; kstep++) {
            int aw = (m0 + grp) * (ASTH / 2) + (s << 4) + (kstep << 3) + t4;
            unsigned xa0 = xu[aw];
            unsigned xa1 = xu[aw + 8 * (ASTH / 2)];
            unsigned xa2 = xu[aw + 4];
            unsigned xa3 = xu[aw + 4 + 8 * (ASTH / 2)];
            unsigned ha0 = hu[aw];
            unsigned ha1 = hu[aw + 8 * (ASTH / 2)];
            unsigned ha2 = hu[aw + 4];
            unsigned ha3 = hu[aw + 4 + 8 * (ASTH / 2)];
#pragma unroll
            for (int f = 0; f < 4; f++) {
                int bw = (nw32 + (f << 3) + grp) * (WSTH / 2) + (kstep << 3) + t4;
                unsigned b0 = ba[bw];
                unsigned b1 = ba[bw + 4];
                asm volatile(
                    "mma.sync.aligned.m16n8k16.row.col.f32.f16.f16.f32 "
                    "{%0,%1,%2,%3},{%4,%5,%6,%7},{%8,%9},{%0,%1,%2,%3};"
                    : "+f"(dx[f][0]), "+f"(dx[f][1]), "+f"(dx[f][2]), "+f"(dx[f][3])
                    : "r"(xa0), "r"(xa1), "r"(xa2), "r"(xa3), "r"(b0), "r"(b1));
                unsigned c0 = bb[bw];
                unsigned c1 = bb[bw + 4];
                asm volatile(
                    "mma.sync.aligned.m16n8k16.row.col.f32.f16.f16.f32 "
                    "{%0,%1,%2,%3},{%4,%5,%6,%7},{%8,%9},{%0,%1,%2,%3};"
                    : "+f"(dh[f][0]), "+f"(dh[f][1]), "+f"(dh[f][2]), "+f"(dh[f][3])
                    : "r"(ha0), "r"(ha1), "r"(ha2), "r"(ha3), "r"(c0), "r"(c1));
            }
        }
    }
}

__global__ __launch_bounds__(NTHREADS, 1) void k_gru(
    float* __restrict__ h, const float* __restrict__ node_type,
    const float* __restrict__ Wih, const float* __restrict__ bhh,
    const float* __restrict__ Wattn, const float* __restrict__ b_attn, int level) {
    extern __shared__ __align__(16) char smb[];
    __half* wsA0 = (__half*)(smb + SMB_WSA0);
    __half* wsA1 = (__half*)(smb + SMB_WSA1);
    __half* wsB0 = (__half*)(smb + SMB_WSB0);
    __half* wsB1 = (__half*)(smb + SMB_WSB1);
    __half* xs   = (__half*)(smb + SMB_XS);
    __half* hs   = (__half*)(smb + SMB_HS);
    float*  hsf  = (float*)(smb + SMB_HSF);
    float*  smnt = (float*)(smb + SMB_NT);
    float*  sbb  = (float*)(smb + SMB_BB);
    float*  sbh  = (float*)(smb + SMB_BH);
    float*  sp1  = (float*)(smb + SMB_SP1);
    float*  sp2  = (float*)(smb + SMB_SP2);
    int*    snode = (int*)(smb + SMB_SNODE);
    float*  sact  = (float*)(smb + SMB_SACT);
    float*  srd   = (float*)(smb + SMB_SRD);
    int*    stype = (int*)(smb + SMB_STYPE);

    int t = threadIdx.x;
    int start = g_node_off[level], end = g_node_off[level + 1];
    int cnt = end - start;
    int ntiles = (cnt + TILE_N - 1) / TILE_N;
    int lane = t & 31;
    int warp = t >> 5;                // 0..15
    int grp = lane >> 2;              // 0..7
    int t4 = lane & 3;                // 0..3
    int m0 = (warp & 3) << 4;         // node base within tile
    int nw32 = (warp >> 2) << 5;      // row base: 0,32,64,96
    float battn = __ldg(b_attn);

    // stage constants once per block
    for (int idx = t; idx < 1152; idx += NTHREADS) {
        int c = idx % 3, r = idx / 3;
        smnt[c * 384 + r] = Wih[r * 131 + 128 + c];
    }
    for (int idx = t; idx < 384; idx += NTHREADS) {
        sbb[idx] = g_bbig[idx];
        sbh[idx] = bhh[idx];
    }

    for (int tile = blockIdx.x; tile < ntiles; tile += gridDim.x) {
        __syncthreads();          // constants ready / prior tile fully done
        if (t < TILE_N) {
            int slot = start + tile * TILE_N + t;
            int node = -1, ty = 0;
            if (slot < end) {
                node = g_node_list[slot];
                float n1 = node_type[(size_t)node * 3 + 1];
                float n2 = node_type[(size_t)node * 3 + 2];
                ty = n1 > 0.5f ? 1 : (n2 > 0.5f ? 2 : 0);
            }
            snode[t] = node; stype[t] = ty;
            sp1[t] = 0.f; sp2[t] = 0.f;
        }
        __syncthreads();

        // fused aggregation + staging: warp w handles nodes 4w..4w+3
#pragma unroll
        for (int j = 0; j < 4; j++) {
            int n = (warp << 2) | j;
            int nodeRaw = snode[n];
            bool valid = nodeRaw >= 0;
            int node = valid ? nodeRaw : 0;
            int r0 = g_row[node], r1 = g_row[node + 1];
            float p2d = g_p2[node];
            float denom = 0.f;
            float4 acc = make_float4(0.f, 0.f, 0.f, 0.f);
            if (valid) {
#pragma unroll 2
                for (int e = r0; e < r1; e++) {
                    int src = __ldg(&g_es[e]);
                    float ee = g_p1[src] + p2d + battn;
                    ee = ee > 0.f ? ee : 0.2f * ee;
                    float ex = __expf(ee);
                    denom += ex;
                    float4 hv = __ldg((const float4*)(h + (size_t)src * H + lane * 4));
                    acc.x += ex * hv.x; acc.y += ex * hv.y;
                    acc.z += ex * hv.z; acc.w += ex * hv.w;
                }
            }
            float act = 0.f, rd = 0.f;
            if (valid && denom > 0.f) { act = 1.f; rd = 1.f / (denom + 1e-16f); }
            int bh2 = n * ASTH + lane * 4;
            *(__half2*)&xs[bh2]     = __floats2half2_rn(acc.x * rd, acc.y * rd);
            *(__half2*)&xs[bh2 + 2] = __floats2half2_rn(acc.z * rd, acc.w * rd);
            float4 hv = *(const float4*)&h[(size_t)node * H + lane * 4];
            *(__half2*)&hs[bh2]     = __floats2half2_rn(hv.x, hv.y);
            *(__half2*)&hs[bh2 + 2] = __floats2half2_rn(hv.z, hv.w);
            *(float4*)&hsf[n * ASTF + lane * 4] = hv;
            if (lane == 0) { sact[n] = act; srd[n] = rd; }
        }
        // (mma_dual entry sync covers staging visibility)

        int ty_lo = 0, ty_hi = 0;
        float rr[4][4], zz[4][4];
        for (int chunk = 0; chunk < 3; chunk++) {
            float dx[4][4], dh[4][4];
#pragma unroll
            for (int f = 0; f < 4; f++)
#pragma unroll
                for (int j = 0; j < 4; j++) { dx[f][j] = 0.f; dh[f][j] = 0.f; }
            mma_dual(dx, dh, chunk * H, xs, hs, wsA0, wsA1, wsB0, wsB1,
                     m0, nw32, grp, t4, t);
            if (chunk == 0) { ty_lo = stype[m0 + grp]; ty_hi = stype[m0 + grp + 8]; }
            int rb = chunk * H;
            if (chunk < 2) {
#pragma unroll
                for (int f = 0; f < 4; f++) {
                    int feat0 = nw32 + (f << 3) + (t4 << 1);
                    float bb0 = sbb[rb + feat0],  bb1 = sbb[rb + feat0 + 1];
                    float bh0 = sbh[rb + feat0],  bh1 = sbh[rb + feat0 + 1];
                    float clo0 = smnt[ty_lo * 384 + rb + feat0];
                    float clo1 = smnt[ty_lo * 384 + rb + feat0 + 1];
                    float chi0 = smnt[ty_hi * 384 + rb + feat0];
                    float chi1 = smnt[ty_hi * 384 + rb + feat0 + 1];
                    float g0 = sig_(dx[f][0] + bb0 + clo0 + dh[f][0] + bh0);
                    float g1 = sig_(dx[f][1] + bb1 + clo1 + dh[f][1] + bh1);
                    float g2 = sig_(dx[f][2] + bb0 + chi0 + dh[f][2] + bh0);
                    float g3 = sig_(dx[f][3] + bb1 + chi1 + dh[f][3] + bh1);
                    if (chunk == 0) { rr[f][0]=g0; rr[f][1]=g1; rr[f][2]=g2; rr[f][3]=g3; }
                    else            { zz[f][0]=g0; zz[f][1]=g1; zz[f][2]=g2; zz[f][3]=g3; }
                }
            } else {
                int nl_lo = m0 + grp, nl_hi = m0 + grp + 8;
                int node_lo = snode[nl_lo], node_hi = snode[nl_hi];
                bool act_lo = sact[nl_lo] > 0.f, act_hi = sact[nl_hi] > 0.f;
                float s1lo = 0.f, s2lo = 0.f, s1hi = 0.f, s2hi = 0.f;
#pragma unroll
                for (int f = 0; f < 4; f++) {
                    int feat0 = nw32 + (f << 3) + (t4 << 1);
                    float bb0 = sbb[rb + feat0],  bb1 = sbb[rb + feat0 + 1];
                    float bh0 = sbh[rb + feat0],  bh1 = sbh[rb + feat0 + 1];
                    float clo0 = smnt[ty_lo * 384 + rb + feat0];
                    float clo1 = smnt[ty_lo * 384 + rb + feat0 + 1];
                    float chi0 = smnt[ty_hi * 384 + rb + feat0];
                    float chi1 = smnt[ty_hi * 384 + rb + feat0 + 1];
                    float n0 = tanh_(dx[f][0] + bb0 + clo0 + rr[f][0] * (dh[f][0] + bh0));
                    float n1 = tanh_(dx[f][1] + bb1 + clo1 + rr[f][1] * (dh[f][1] + bh1));
                    float n2 = tanh_(dx[f][2] + bb0 + chi0 + rr[f][2] * (dh[f][2] + bh0));
                    float n3 = tanh_(dx[f][3] + bb1 + chi1 + rr[f][3] * (dh[f][3] + bh1));
                    float ho0 = hsf[nl_lo * ASTF + feat0];
                    float ho1 = hsf[nl_lo * ASTF + feat0 + 1];
                    float ho2 = hsf[nl_hi * ASTF + feat0];
                    float ho3 = hsf[nl_hi * ASTF + feat0 + 1];
                    float v0 = (1.f - zz[f][0]) * n0 + zz[f][0] * ho0;
                    float v1 = (1.f - zz[f][1]) * n1 + zz[f][1] * ho1;
                    float v2 = (1.f - zz[f][2]) * n2 + zz[f][2] * ho2;
                    float v3 = (1.f - zz[f][3]) * n3 + zz[f][3] * ho3;
                    if (act_lo)
                        *(float2*)&h[(size_t)node_lo * H + feat0] = make_float2(v0, v1);
                    if (act_hi)
                        *(float2*)&h[(size_t)node_hi * H + feat0] = make_float2(v2, v3);
                    float2 wa1 = *(const float2*)&Wattn[feat0];
                    float2 wa2 = *(const float2*)&Wattn[H + feat0];
                    s1lo += v0 * wa1.x + v1 * wa1.y;
                    s2lo += v0 * wa2.x + v1 * wa2.y;
                    s1hi += v2 * wa1.x + v3 * wa1.y;
                    s2hi += v2 * wa2.x + v3 * wa2.y;
                }
                atomicAdd(&sp1[nl_lo], s1lo);
                atomicAdd(&sp2[nl_lo], s2lo);
                atomicAdd(&sp1[nl_hi], s1hi);
                atomicAdd(&sp2[nl_hi], s2hi);
            }
        }
        __syncthreads();
        if (t < TILE_N && sact[t] > 0.f) {
            int node = snode[t];
            g_p1[node] = sp1[t];
            g_p2[node] = sp2[t];
        }
    }
}

// ---------------- launch ----------------
extern "C" void kernel_launch(void* const* d_in, const int* in_sizes, int n_in,
                              void* d_out, int out_size) {
    const float* node_embedding = (const float*)d_in[0];
    const float* node_type      = (const float*)d_in[1];
    const float* W_attn         = (const float*)d_in[2];
    const float* b_attn         = (const float*)d_in[3];
    const float* W_msg          = (const float*)d_in[4];
    const float* b_msg          = (const float*)d_in[5];
    const float* W_ih           = (const float*)d_in[6];
    const float* W_hh           = (const float*)d_in[7];
    const float* b_ih           = (const float*)d_in[8];
    const float* b_hh           = (const float*)d_in[9];
    const int*   edge_src       = (const int*)d_in[10];
    const int*   edge_dst       = (const int*)d_in[11];
    const int*   fnl            = (const int*)d_in[12];
    float* h = (float*)d_out;

    cudaFuncSetAttribute(k_gru, cudaFuncAttributeMaxDynamicSharedMemorySize, SMB_TOTAL);

    k_setup<<<384, 128>>>(W_ih, W_msg, b_ih, b_msg, W_hh);
    k_degcount<<<1563, 256>>>(fnl, edge_dst);
    k_scandeg<<<1, 1024>>>();
    k_scatter<<<1758, 256>>>(fnl, edge_src, edge_dst);
    k_init<<<6250, 256>>>(node_embedding, W_attn, h);

    for (int k = 1; k < DEPTH; k++) {
        k_gru<<<148, NTHREADS, SMB_TOTAL>>>(h, node_type, W_ih, b_hh, W_attn,
                                            b_attn, k);
    }
}